// round 13
// baseline (speedup 1.0000x reference)
#include <cuda_runtime.h>
#include <cuda_fp16.h>
#include <cstdint>

#define BATCH  16384
#define TSTEPS 50
#define HIDDEN 256
#define XCOLS  72       // obs64 | act8, unpadded
#define NSTAGE 5        // 5 x K64 covers k[0,320); tail K8 covers k[320,328)
#define NGATE  1024
#define KTOT   328      // x[0,72) | h[72,328)
#define MTILES 128
#define NTILES 16
#define TILES_PER_STEP (MTILES * NTILES)   // 2048

// ---------------- device scratch ----------------
__device__ __align__(16) __half g_Wb_hi[NGATE * KTOT];
__device__ __align__(16) __half g_Wb_lo[NGATE * KTOT];
__device__ float g_bias[NGATE];
__device__ __align__(16) float  g_c[BATCH * HIDDEN];
__device__ __align__(16) __half g_h[2][BATCH * HIDDEN];
__device__ __align__(16) __half g_x72[(size_t)TSTEPS * BATCH * XCOLS];
__device__ unsigned int g_cnt[TSTEPS * MTILES];   // n-tiles done per (t, mtile)

// ---------------- helpers ----------------
__device__ __forceinline__ uint32_t smem_u32(const void* p) {
    uint32_t a;
    asm("{ .reg .u64 t; cvta.to.shared.u64 t, %1; cvt.u32.u64 %0, t; }" : "=r"(a) : "l"(p));
    return a;
}
__device__ __forceinline__ void cpasync16(uint32_t dst, const void* src) {
    asm volatile("cp.async.cg.shared.global [%0], [%1], 16;" :: "r"(dst), "l"(src));
}
#define CP_COMMIT() asm volatile("cp.async.commit_group;" ::: "memory")
#define CP_WAIT1()  asm volatile("cp.async.wait_group 1;" ::: "memory")
#define CP_WAIT0()  asm volatile("cp.async.wait_group 0;" ::: "memory")

__device__ __forceinline__ void ldsm4(uint32_t* r, uint32_t addr) {
    asm volatile("ldmatrix.sync.aligned.m8n8.x4.shared.b16 {%0,%1,%2,%3}, [%4];"
                 : "=r"(r[0]), "=r"(r[1]), "=r"(r[2]), "=r"(r[3]) : "r"(addr));
}
__device__ __forceinline__ void ldsm2(uint32_t* r, uint32_t addr) {
    asm volatile("ldmatrix.sync.aligned.m8n8.x2.shared.b16 {%0,%1}, [%2];"
                 : "=r"(r[0]), "=r"(r[1]) : "r"(addr));
}
__device__ __forceinline__ void mma16816(float* d, const uint32_t* a, uint32_t b0, uint32_t b1) {
    asm volatile("mma.sync.aligned.m16n8k16.row.col.f32.f16.f16.f32 "
                 "{%0,%1,%2,%3}, {%4,%5,%6,%7}, {%8,%9}, {%0,%1,%2,%3};"
                 : "+f"(d[0]), "+f"(d[1]), "+f"(d[2]), "+f"(d[3])
                 : "r"(a[0]), "r"(a[1]), "r"(a[2]), "r"(a[3]), "r"(b0), "r"(b1));
}
__device__ __forceinline__ float sigm(float x)   { return 1.f / (1.f + __expf(-x)); }
__device__ __forceinline__ float tanhf_(float x) { return 1.f - 2.f / (__expf(2.f * x) + 1.f); }

// ---------------- init kernels ----------------
__global__ void zero_state_kernel() {
    size_t i0 = (size_t)blockIdx.x * blockDim.x + threadIdx.x;
    size_t st = (size_t)gridDim.x * blockDim.x;
    const __half z = __float2half(0.f);
    for (size_t i = i0; i < (size_t)BATCH * HIDDEN; i += st) {
        g_c[i] = 0.f; g_h[0][i] = z;
    }
    for (size_t i = i0; i < TSTEPS * MTILES; i += st) g_cnt[i] = 0u;
}

// Column permutation for N-tile 64, warp half 32 (R8 mapping):
// n = nt*64 + hf*32 + gate*8 + u  ->  orig col gate*256 + nt*16 + hf*8 + u
// K layout: k<72 -> x (obs|act), k in [72,328) -> h
__global__ void prep_weights_kernel(const float* __restrict__ Wi, const float* __restrict__ Wh,
                                    const float* __restrict__ bias) {
    int i0 = blockIdx.x * blockDim.x + threadIdx.x;
    int st = gridDim.x * blockDim.x;
    for (int idx = i0; idx < NGATE * KTOT; idx += st) {
        int n = idx / KTOT, k = idx - n * KTOT;
        int nt = n >> 6, rem = n & 63, hf = rem >> 5, ncol = rem & 31;
        int gate = ncol >> 3, u = ncol & 7;
        int src = gate * 256 + nt * 16 + hf * 8 + u;
        float w = (k < 72) ? Wi[k * NGATE + src] : Wh[(k - 72) * NGATE + src];
        __half hi = __float2half_rn(w);
        g_Wb_hi[n * KTOT + k] = hi;
        g_Wb_lo[n * KTOT + k] = __float2half_rn(w - __half2float(hi));
    }
    if (i0 < NGATE) {
        int nt = i0 >> 6, rem = i0 & 63, hf = rem >> 5, ncol = rem & 31;
        int gate = ncol >> 3, u = ncol & 7;
        g_bias[i0] = bias[gate * 256 + nt * 16 + hf * 8 + u];
    }
}

// g_x72: [t][b][72], obs 0..63 | act 64..71
__global__ void prep_x_kernel(const float* __restrict__ obs, const float* __restrict__ act) {
    size_t i0 = (size_t)blockIdx.x * blockDim.x + threadIdx.x;
    size_t st = (size_t)gridDim.x * blockDim.x;
    const size_t N = (size_t)TSTEPS * BATCH * XCOLS;
    for (size_t i = i0; i < N; i += st) {
        int col = (int)(i % XCOLS);
        size_t m = i / XCOLS;
        int b = (int)(m & (BATCH - 1));
        int t = (int)(m >> 14);
        float v = (col < 64) ? obs[((size_t)b * TSTEPS + t) * 64 + col]
                             : act[((size_t)b * TSTEPS + t) * 8 + (col - 64)];
        g_x72[i] = __float2half_rn(v);
    }
}

// ---------------- streamed LSTM tile kernel ----------------
// One launch, 50*2048 tiles, bid = t*2048 + tile (t-major).
// Tile (t, mt, nt) waits on g_cnt[t-1][mt] == 16, computes, signals g_cnt[t][mt].
// CTA tile 128(M) x 64(N); per stage A 16K | B_hi 8K | B_lo 8K = 32K, double buffered.
static constexpr int STG_BYTES = 32768;
static constexpr int S_A    = 0;
static constexpr int S_B_HI = 16384;
static constexpr int S_B_LO = 24576;
static constexpr int S_TAIL = 2 * STG_BYTES;          // 65536
static constexpr int T_A    = 0, T_B_HI = 2048, T_B_LO = 3072;
static constexpr int S_BIAS = S_TAIL + 4096;          // 69632
static constexpr int STEP_SMEM = S_BIAS + 256;        // 69888  (x3 = 205KB/SM)

// stage s covers k [s*64, s*64+64): k<72 -> x72, else h (k-72)
__device__ __forceinline__ void load_stage(
    uint32_t sb, int m0, int nb, int s, int tid,
    const __half* __restrict__ xh, const __half* __restrict__ hin)
{
    const uint32_t base = sb + (uint32_t)(s & 1) * STG_BYTES;
    #pragma unroll
    for (int it = 0; it < 4; it++) {            // A: 128 rows x 8 quads
        int q = tid + it * 256;
        int r = q >> 3, c = q & 7;
        int k = s * 64 + c * 8;
        uint32_t d = (uint32_t)(r * 128) + (uint32_t)((c * 16) ^ ((r & 7) * 16));
        const __half* sa = (k < 72)
            ? xh  + (size_t)(m0 + r) * XCOLS + k
            : hin + (size_t)(m0 + r) * HIDDEN + (k - 72);
        cpasync16(base + S_A + d, sa);
    }
    #pragma unroll
    for (int it = 0; it < 2; it++) {            // B: 64 rows x 8 quads (hi, lo)
        int q = tid + it * 256;
        int r = q >> 3, c = q & 7;
        int k = s * 64 + c * 8;
        uint32_t d = (uint32_t)(r * 128) + (uint32_t)((c * 16) ^ ((r & 7) * 16));
        size_t ob = (size_t)(nb + r) * KTOT + k;
        cpasync16(base + S_B_HI + d, g_Wb_hi + ob);
        cpasync16(base + S_B_LO + d, g_Wb_lo + ob);
    }
}

// tail: k [320, 328), A 128 rows / B 64 rows x 8 cols, 16B rows, no swizzle
__device__ __forceinline__ void load_tail(
    uint32_t sb, int m0, int nb, int tid, const __half* __restrict__ hin)
{
    if (tid < 128) {
        int r = tid;
        cpasync16(sb + S_TAIL + T_A + (uint32_t)(r * 16),
                  hin + (size_t)(m0 + r) * HIDDEN + (320 - 72));
    }
    if (tid < 64) {
        int r = tid;
        size_t ob = (size_t)(nb + r) * KTOT + 320;
        cpasync16(sb + S_TAIL + T_B_HI + (uint32_t)(r * 16), g_Wb_hi + ob);
        cpasync16(sb + S_TAIL + T_B_LO + (uint32_t)(r * 16), g_Wb_lo + ob);
    }
}

__global__ __launch_bounds__(256, 3)
void lstm_stream_kernel() {
    extern __shared__ char smem[];
    const int tid = threadIdx.x, w = tid >> 5, lane = tid & 31;
    const int bid = blockIdx.x;
    const int t = bid >> 11;                   // bid / 2048
    const int tile = bid & (TILES_PER_STEP - 1);
    const int mt = tile >> 4, nt = tile & 15;
    const int m0 = mt * 128, nb = nt * 64;
    const int ip = t & 1;
    const __half* __restrict__ hin = g_h[ip];
    __half* __restrict__ hout = g_h[ip ^ 1];

    uint32_t sb = smem_u32(smem);
    float* bias_s = (float*)(smem + S_BIAS);
    if (tid < 64) bias_s[tid] = g_bias[nb + tid];

    const __half* xh = g_x72 + (size_t)t * BATCH * XCOLS;

    // stage 0 is pure-x (k<64) + weights: no dependency on h_{t-1} -> issue before spin
    load_stage(sb, m0, nb, 0, tid, xh, hin);
    CP_COMMIT();

    // ---- dependency wait: h_{t-1}[m-rows] from the 16 (t-1, mt, *) tiles ----
    if (t > 0) {
        if (tid == 0) {
            while (atomicAdd(&g_cnt[(t - 1) * MTILES + mt], 0u) < 16u)
                __nanosleep(64);
            __threadfence();
        }
        __syncthreads();
    }

    load_tail(sb, m0, nb, tid, hin);

    float acc[32];
    #pragma unroll
    for (int i = 0; i < 32; i++) acc[i] = 0.f;

    // warp tile: 32 (M) x 32 (N); 8 warps = 4M x 2N
    const int mwarp = (w >> 1) * 32, nwarp = (w & 1) * 32;
    const int laneA_row = (lane & 7) + ((lane >> 3) & 1) * 8;
    const uint32_t laneA_col = (uint32_t)((lane >> 4) * 16);
    const int laneB_row = (lane & 7) + ((lane >> 4) << 3);
    const uint32_t laneB_col = (uint32_t)(((lane >> 3) & 1) * 16);

    #pragma unroll 1
    for (int s = 0; s < NSTAGE; s++) {
        if (s + 1 < NSTAGE) {
            load_stage(sb, m0, nb, s + 1, tid, xh, hin);
            CP_COMMIT();
            CP_WAIT1();
        } else {
            CP_WAIT0();
        }
        __syncthreads();

        const uint32_t base = sb + (uint32_t)(s & 1) * STG_BYTES;
        #pragma unroll
        for (int kk = 0; kk < 4; kk++) {
            uint32_t af[2][4];
            #pragma unroll
            for (int mm = 0; mm < 2; mm++) {
                int rA = mwarp + mm * 16 + laneA_row;
                uint32_t ca = ((uint32_t)(kk * 32) + laneA_col) ^ (uint32_t)((rA & 7) * 16);
                ldsm4(af[mm], base + S_A + (uint32_t)(rA * 128) + ca);
            }
            #pragma unroll
            for (int bn = 0; bn < 2; bn++) {
                int rB = nwarp + bn * 16 + laneB_row;
                uint32_t cb = ((uint32_t)(kk * 32) + laneB_col) ^ (uint32_t)((rB & 7) * 16);
                uint32_t bh[4], bl[4];
                ldsm4(bh, base + S_B_HI + (uint32_t)(rB * 128) + cb);
                ldsm4(bl, base + S_B_LO + (uint32_t)(rB * 128) + cb);
                #pragma unroll
                for (int mm = 0; mm < 2; mm++) {
                    float* a0 = acc + ((mm * 2 + bn) * 2 + 0) * 4;
                    float* a1 = acc + ((mm * 2 + bn) * 2 + 1) * 4;
                    mma16816(a0, af[mm], bh[0], bh[1]);
                    mma16816(a0, af[mm], bl[0], bl[1]);
                    mma16816(a1, af[mm], bh[2], bh[3]);
                    mma16816(a1, af[mm], bl[2], bl[3]);
                }
            }
        }
        __syncthreads();
    }

    // ---- tail K8 pass (k 320..327) ----
    {
        const int lrow = lane & 15;
        #pragma unroll
        for (int mm = 0; mm < 2; mm++) {
            int rA = mwarp + mm * 16 + lrow;
            uint32_t a2[2];
            ldsm2(a2, sb + S_TAIL + T_A + (uint32_t)(rA * 16));
            uint32_t aT[4] = {a2[0], a2[1], 0u, 0u};
            #pragma unroll
            for (int bn = 0; bn < 2; bn++) {
                int rB = nwarp + bn * 16 + lrow;
                uint32_t b2h[2], b2l[2];
                ldsm2(b2h, sb + S_TAIL + T_B_HI + (uint32_t)(rB * 16));
                ldsm2(b2l, sb + S_TAIL + T_B_LO + (uint32_t)(rB * 16));
                float* a0 = acc + ((mm * 2 + bn) * 2 + 0) * 4;
                float* a1 = acc + ((mm * 2 + bn) * 2 + 1) * 4;
                mma16816(a0, aT, b2h[0], 0u);
                mma16816(a0, aT, b2l[0], 0u);
                mma16816(a1, aT, b2h[1], 0u);
                mma16816(a1, aT, b2l[1], 0u);
            }
        }
    }

    // ---- fused LSTM epilogue (R8 mapping: gate = bn*2 + a01, u = c) ----
    const int c = 2 * (lane & 3);
    #pragma unroll
    for (int mm = 0; mm < 2; mm++) {
        #pragma unroll
        for (int rs = 0; rs < 2; rs++) {
            const int row = m0 + mwarp + mm * 16 + (lane >> 2) + rs * 8;
            float gv[4][2];
            #pragma unroll
            for (int gate = 0; gate < 4; gate++) {
                int bn = gate >> 1, a01 = gate & 1;
                int ai = ((mm * 2 + bn) * 2 + a01) * 4 + rs * 2;
                int bcol = (w & 1) * 32 + gate * 8 + c;
                gv[gate][0] = acc[ai + 0] + bias_s[bcol];
                gv[gate][1] = acc[ai + 1] + bias_s[bcol + 1];
            }
            size_t cix = (size_t)row * HIDDEN + nt * 16 + (w & 1) * 8 + c;
            float2 cv = *reinterpret_cast<float2*>(g_c + cix);
            float nc0 = sigm(gv[1][0]) * cv.x + sigm(gv[0][0]) * tanhf_(gv[2][0]);
            float nc1 = sigm(gv[1][1]) * cv.y + sigm(gv[0][1]) * tanhf_(gv[2][1]);
            *reinterpret_cast<float2*>(g_c + cix) = make_float2(nc0, nc1);
            float h0 = sigm(gv[3][0]) * tanhf_(nc0);
            float h1 = sigm(gv[3][1]) * tanhf_(nc1);
            *reinterpret_cast<__half2*>(hout + cix) = __floats2half2_rn(h0, h1);
        }
    }

    // ---- signal ----
    __syncthreads();
    if (tid == 0) {
        __threadfence();
        atomicAdd(&g_cnt[t * MTILES + mt], 1u);
    }
}

// ---------------- MLP heads ----------------
static constexpr int H_W1M = 0, H_W2M = 16384, H_W3M = 20480;
static constexpr int H_W1L = 21504, H_W2L = 29696, H_W3L = 30720;
static constexpr int H_B1M = 31232, H_B2M = 31296, H_B3M = 31360;
static constexpr int H_B1L = 31376, H_B2L = 31408, H_B3L = 31440;
static constexpr int HEADS_SMEM = 31456 * 4;

__global__ __launch_bounds__(128, 1)
void heads_kernel(const float* __restrict__ mW1, const float* __restrict__ mb1,
                  const float* __restrict__ mW2, const float* __restrict__ mb2,
                  const float* __restrict__ mW3, const float* __restrict__ mb3,
                  const float* __restrict__ lW1, const float* __restrict__ lb1,
                  const float* __restrict__ lW2, const float* __restrict__ lb2,
                  const float* __restrict__ lW3, const float* __restrict__ lb3,
                  float* __restrict__ out) {
    extern __shared__ float sw[];
    const int tid = threadIdx.x;
    for (int i = tid; i < 16384; i += 128) sw[H_W1M + i] = mW1[i];
    for (int i = tid; i < 4096;  i += 128) sw[H_W2M + i] = mW2[i];
    for (int i = tid; i < 1024;  i += 128) sw[H_W3M + i] = mW3[i];
    for (int i = tid; i < 8192;  i += 128) sw[H_W1L + i] = lW1[i];
    for (int i = tid; i < 1024;  i += 128) sw[H_W2L + i] = lW2[i];
    for (int i = tid; i < 512;   i += 128) sw[H_W3L + i] = lW3[i];
    if (tid < 64) { sw[H_B1M + tid] = mb1[tid]; sw[H_B2M + tid] = mb2[tid]; }
    if (tid < 32) { sw[H_B1L + tid] = lb1[tid]; sw[H_B2L + tid] = lb2[tid]; }
    if (tid < 16) { sw[H_B3M + tid] = mb3[tid]; sw[H_B3L + tid] = lb3[tid]; }
    __syncthreads();

    const int row = blockIdx.x * 128 + tid;
    const __half* hh = g_h[0];   // T=50 even -> final h parity 0
    const size_t hbase = (size_t)row * HIDDEN;

    float x1[64], y1[32];
    #pragma unroll
    for (int j = 0; j < 64; j++) x1[j] = sw[H_B1M + j];
    #pragma unroll
    for (int j = 0; j < 32; j++) y1[j] = sw[H_B1L + j];

    for (int kc = 0; kc < 16; kc++) {
        float hk[16];
        #pragma unroll
        for (int n = 0; n < 16; n++) hk[n] = __half2float(hh[hbase + kc * 16 + n]);
        #pragma unroll
        for (int n = 0; n < 16; n++) {
            const int k = kc * 16 + n;
            #pragma unroll
            for (int j4 = 0; j4 < 16; j4++) {
                float4 wv = *reinterpret_cast<const float4*>(sw + H_W1M + k * 64 + j4 * 4);
                x1[j4*4+0] += hk[n] * wv.x; x1[j4*4+1] += hk[n] * wv.y;
                x1[j4*4+2] += hk[n] * wv.z; x1[j4*4+3] += hk[n] * wv.w;
            }
            #pragma unroll
            for (int j4 = 0; j4 < 8; j4++) {
                float4 wv = *reinterpret_cast<const float4*>(sw + H_W1L + k * 32 + j4 * 4);
                y1[j4*4+0] += hk[n] * wv.x; y1[j4*4+1] += hk[n] * wv.y;
                y1[j4*4+2] += hk[n] * wv.z; y1[j4*4+3] += hk[n] * wv.w;
            }
        }
    }

    float x2[64];
    #pragma unroll
    for (int j = 0; j < 64; j++) { x1[j] = fmaxf(x1[j], 0.f); x2[j] = sw[H_B2M + j]; }
    #pragma unroll
    for (int k = 0; k < 64; k++) {
        #pragma unroll
        for (int j4 = 0; j4 < 16; j4++) {
            float4 wv = *reinterpret_cast<const float4*>(sw + H_W2M + k * 64 + j4 * 4);
            x2[j4*4+0] += x1[k] * wv.x; x2[j4*4+1] += x1[k] * wv.y;
            x2[j4*4+2] += x1[k] * wv.z; x2[j4*4+3] += x1[k] * wv.w;
        }
    }
    float mu[16];
    #pragma unroll
    for (int j = 0; j < 16; j++) mu[j] = sw[H_B3M + j];
    #pragma unroll
    for (int k = 0; k < 64; k++) {
        float xv = fmaxf(x2[k], 0.f);
        #pragma unroll
        for (int j4 = 0; j4 < 4; j4++) {
            float4 wv = *reinterpret_cast<const float4*>(sw + H_W3M + k * 16 + j4 * 4);
            mu[j4*4+0] += xv * wv.x; mu[j4*4+1] += xv * wv.y;
            mu[j4*4+2] += xv * wv.z; mu[j4*4+3] += xv * wv.w;
        }
    }
    #pragma unroll
    for (int j4 = 0; j4 < 4; j4++)
        *reinterpret_cast<float4*>(out + (size_t)row * 16 + j4 * 4) =
            make_float4(mu[j4*4], mu[j4*4+1], mu[j4*4+2], mu[j4*4+3]);

    float y2[32];
    #pragma unroll
    for (int j = 0; j < 32; j++) { y1[j] = fmaxf(y1[j], 0.f); y2[j] = sw[H_B2L + j]; }
    #pragma unroll
    for (int k = 0; k < 32; k++) {
        #pragma unroll
        for (int j4 = 0; j4 < 8; j4++) {
            float4 wv = *reinterpret_cast<const float4*>(sw + H_W2L + k * 32 + j4 * 4);
            y2[j4*4+0] += y1[k] * wv.x; y2[j4*4+1] += y1[k] * wv.y;
            y2[j4*4+2] += y1[k] * wv.z; y2[j4*4+3] += y1[k] * wv.w;
        }
    }
    float ls[16];
    #pragma unroll
    for (int j = 0; j < 16; j++) ls[j] = sw[H_B3L + j];
    #pragma unroll
    for (int k = 0; k < 32; k++) {
        float xv = fmaxf(y2[k], 0.f);
        #pragma unroll
        for (int j4 = 0; j4 < 4; j4++) {
            float4 wv = *reinterpret_cast<const float4*>(sw + H_W3L + k * 16 + j4 * 4);
            ls[j4*4+0] += xv * wv.x; ls[j4*4+1] += xv * wv.y;
            ls[j4*4+2] += xv * wv.z; ls[j4*4+3] += xv * wv.w;
        }
    }
    float* sig = out + (size_t)BATCH * 16 + (size_t)row * 16;
    #pragma unroll
    for (int j = 0; j < 16; j++)
        sig[j] = __expf(fminf(fmaxf(ls[j], -10.f), 2.f));
}

// ---------------- launch ----------------
extern "C" void kernel_launch(void* const* d_in, const int* in_sizes, int n_in,
                              void* d_out, int out_size) {
    const float* obs = (const float*)d_in[0];
    const float* act = (const float*)d_in[1];
    const float* Wi  = (const float*)d_in[2];
    const float* Wh  = (const float*)d_in[3];
    const float* b   = (const float*)d_in[4];
    const float* mW1 = (const float*)d_in[5],  *mb1 = (const float*)d_in[6];
    const float* mW2 = (const float*)d_in[7],  *mb2 = (const float*)d_in[8];
    const float* mW3 = (const float*)d_in[9],  *mb3 = (const float*)d_in[10];
    const float* lW1 = (const float*)d_in[11], *lb1 = (const float*)d_in[12];
    const float* lW2 = (const float*)d_in[13], *lb2 = (const float*)d_in[14];
    const float* lW3 = (const float*)d_in[15], *lb3 = (const float*)d_in[16];
    float* out = (float*)d_out;

    cudaFuncSetAttribute(lstm_stream_kernel,
                         cudaFuncAttributeMaxDynamicSharedMemorySize, STEP_SMEM);
    cudaFuncSetAttribute(heads_kernel,
                         cudaFuncAttributeMaxDynamicSharedMemorySize, HEADS_SMEM);

    zero_state_kernel<<<512, 256>>>();
    prep_weights_kernel<<<384, 256>>>(Wi, Wh, b);
    prep_x_kernel<<<4096, 256>>>(obs, act);
    lstm_stream_kernel<<<TSTEPS * TILES_PER_STEP, 256, STEP_SMEM>>>();
    heads_kernel<<<BATCH / 128, 128, HEADS_SMEM>>>(mW1, mb1, mW2, mb2, mW3, mb3,
                                                   lW1, lb1, lW2, lb2, lW3, lb3, out);
}

// round 14
// speedup vs baseline: 1.0553x; 1.0553x over previous
#include <cuda_runtime.h>
#include <cuda_fp16.h>
#include <cstdint>

#define BATCH  16384
#define TSTEPS 50
#define HIDDEN 256
#define XCOLS  72       // obs64 | act8, unpadded
#define NSTAGE 5        // 5 x K64 covers k[0,320); tail K8 covers k[320,328)
#define NGATE  1024
#define KTOT   328      // x[0,72) | h[72,328)
#define MTILES 128
#define NTILES 8
#define TILES_PER_STEP (MTILES * NTILES)   // 1024

// ---------------- device scratch ----------------
__device__ __align__(16) __half g_Wb_hi[NGATE * KTOT];
__device__ __align__(16) __half g_Wb_lo[NGATE * KTOT];
__device__ float g_bias[NGATE];
__device__ __align__(16) float  g_c[BATCH * HIDDEN];
__device__ __align__(16) __half g_h[2][BATCH * HIDDEN];
__device__ __align__(16) __half g_x72[(size_t)TSTEPS * BATCH * XCOLS];
__device__ unsigned int g_cnt[TSTEPS * MTILES];   // n-tiles done per (t, mtile)

// ---------------- helpers ----------------
__device__ __forceinline__ uint32_t smem_u32(const void* p) {
    uint32_t a;
    asm("{ .reg .u64 t; cvta.to.shared.u64 t, %1; cvt.u32.u64 %0, t; }" : "=r"(a) : "l"(p));
    return a;
}
__device__ __forceinline__ void cpasync16(uint32_t dst, const void* src) {
    asm volatile("cp.async.cg.shared.global [%0], [%1], 16;" :: "r"(dst), "l"(src));
}
#define CP_COMMIT() asm volatile("cp.async.commit_group;" ::: "memory")
#define CP_WAIT1()  asm volatile("cp.async.wait_group 1;" ::: "memory")
#define CP_WAIT0()  asm volatile("cp.async.wait_group 0;" ::: "memory")

__device__ __forceinline__ void ldsm4(uint32_t* r, uint32_t addr) {
    asm volatile("ldmatrix.sync.aligned.m8n8.x4.shared.b16 {%0,%1,%2,%3}, [%4];"
                 : "=r"(r[0]), "=r"(r[1]), "=r"(r[2]), "=r"(r[3]) : "r"(addr));
}
__device__ __forceinline__ void ldsm2(uint32_t* r, uint32_t addr) {
    asm volatile("ldmatrix.sync.aligned.m8n8.x2.shared.b16 {%0,%1}, [%2];"
                 : "=r"(r[0]), "=r"(r[1]) : "r"(addr));
}
__device__ __forceinline__ void mma16816(float* d, const uint32_t* a, uint32_t b0, uint32_t b1) {
    asm volatile("mma.sync.aligned.m16n8k16.row.col.f32.f16.f16.f32 "
                 "{%0,%1,%2,%3}, {%4,%5,%6,%7}, {%8,%9}, {%0,%1,%2,%3};"
                 : "+f"(d[0]), "+f"(d[1]), "+f"(d[2]), "+f"(d[3])
                 : "r"(a[0]), "r"(a[1]), "r"(a[2]), "r"(a[3]), "r"(b0), "r"(b1));
}
__device__ __forceinline__ float sigm(float x)   { return 1.f / (1.f + __expf(-x)); }
__device__ __forceinline__ float tanhf_(float x) { return 1.f - 2.f / (__expf(2.f * x) + 1.f); }

// ---------------- init kernels ----------------
__global__ void zero_state_kernel() {
    size_t i0 = (size_t)blockIdx.x * blockDim.x + threadIdx.x;
    size_t st = (size_t)gridDim.x * blockDim.x;
    const __half z = __float2half(0.f);
    for (size_t i = i0; i < (size_t)BATCH * HIDDEN; i += st) {
        g_c[i] = 0.f; g_h[0][i] = z;
    }
    for (size_t i = i0; i < TSTEPS * MTILES; i += st) g_cnt[i] = 0u;
}

// Column permutation for warp tile 32x64 over N-tile 128:
// n = nb8*128 + hf*64 + gate*16 + u  ->  orig col gate*256 + nb8*32 + hf*16 + u
// K layout: k<72 -> x (obs|act), k in [72,328) -> h
__global__ void prep_weights_kernel(const float* __restrict__ Wi, const float* __restrict__ Wh,
                                    const float* __restrict__ bias) {
    int i0 = blockIdx.x * blockDim.x + threadIdx.x;
    int st = gridDim.x * blockDim.x;
    for (int idx = i0; idx < NGATE * KTOT; idx += st) {
        int n = idx / KTOT, k = idx - n * KTOT;
        int nb8 = n >> 7, rem = n & 127, hf = rem >> 6, ncol = rem & 63;
        int gate = ncol >> 4, u = ncol & 15;
        int src = gate * 256 + nb8 * 32 + hf * 16 + u;
        float w = (k < 72) ? Wi[k * NGATE + src] : Wh[(k - 72) * NGATE + src];
        __half hi = __float2half_rn(w);
        g_Wb_hi[n * KTOT + k] = hi;
        g_Wb_lo[n * KTOT + k] = __float2half_rn(w - __half2float(hi));
    }
    if (i0 < NGATE) {
        int nb8 = i0 >> 7, rem = i0 & 127, hf = rem >> 6, ncol = rem & 63;
        int gate = ncol >> 4, u = ncol & 15;
        g_bias[i0] = bias[gate * 256 + nb8 * 32 + hf * 16 + u];
    }
}

// g_x72: [t][b][72], obs 0..63 | act 64..71
__global__ void prep_x_kernel(const float* __restrict__ obs, const float* __restrict__ act) {
    size_t i0 = (size_t)blockIdx.x * blockDim.x + threadIdx.x;
    size_t st = (size_t)gridDim.x * blockDim.x;
    const size_t N = (size_t)TSTEPS * BATCH * XCOLS;
    for (size_t i = i0; i < N; i += st) {
        int col = (int)(i % XCOLS);
        size_t m = i / XCOLS;
        int b = (int)(m & (BATCH - 1));
        int t = (int)(m >> 14);
        float v = (col < 64) ? obs[((size_t)b * TSTEPS + t) * 64 + col]
                             : act[((size_t)b * TSTEPS + t) * 8 + (col - 64)];
        g_x72[i] = __float2half_rn(v);
    }
}

// ---------------- streamed LSTM tile kernel (R12 config + pre-spin stage-0) ----------------
static constexpr int STG_BYTES = 49152;
static constexpr int S_A    = 0;
static constexpr int S_B_HI = 16384;
static constexpr int S_B_LO = 32768;
static constexpr int S_TAIL = 2 * STG_BYTES;          // 98304
static constexpr int T_A    = 0, T_B_HI = 2048, T_B_LO = 4096;
static constexpr int S_BIAS = S_TAIL + 6144;          // 104448
static constexpr int STEP_SMEM = S_BIAS + 512;        // 104960

// stage s covers k [s*64, s*64+64): k<72 -> x72, else h (k-72)
// stage 0 (k 0..63) touches only x -> safe to issue before the dependency wait
__device__ __forceinline__ void load_stage(
    uint32_t sb, int m0, int nb, int s, int tid,
    const __half* __restrict__ xh, const __half* __restrict__ hin)
{
    const uint32_t base = sb + (uint32_t)(s & 1) * STG_BYTES;
    #pragma unroll
    for (int it = 0; it < 4; it++) {
        int q = tid + it * 256;                 // 1024 quads: 128 rows x 8
        int r = q >> 3, c = q & 7;
        int k = s * 64 + c * 8;
        uint32_t d = (uint32_t)(r * 128) + (uint32_t)((c * 16) ^ ((r & 7) * 16));
        const __half* sa = (k < 72)
            ? xh  + (size_t)(m0 + r) * XCOLS + k
            : hin + (size_t)(m0 + r) * HIDDEN + (k - 72);
        cpasync16(base + S_A + d, sa);
        size_t ob = (size_t)(nb + r) * KTOT + k;
        cpasync16(base + S_B_HI + d, g_Wb_hi + ob);
        cpasync16(base + S_B_LO + d, g_Wb_lo + ob);
    }
}

// tail: k [320, 328), 128 rows x 8 cols, 16B rows, no swizzle (h-dependent)
__device__ __forceinline__ void load_tail(
    uint32_t sb, int m0, int nb, int tid, const __half* __restrict__ hin)
{
    if (tid < 128) {
        int r = tid;
        cpasync16(sb + S_TAIL + T_A + (uint32_t)(r * 16),
                  hin + (size_t)(m0 + r) * HIDDEN + (320 - 72));
        size_t ob = (size_t)(nb + r) * KTOT + 320;
        cpasync16(sb + S_TAIL + T_B_HI + (uint32_t)(r * 16), g_Wb_hi + ob);
        cpasync16(sb + S_TAIL + T_B_LO + (uint32_t)(r * 16), g_Wb_lo + ob);
    }
}

__global__ __launch_bounds__(256, 2)
void lstm_stream_kernel() {
    extern __shared__ char smem[];
    const int tid = threadIdx.x, w = tid >> 5, lane = tid & 31;
    const int bid = blockIdx.x;
    const int t = bid >> 10;                   // bid / 1024
    const int tile = bid & (TILES_PER_STEP - 1);
    const int mt = tile >> 3, nt = tile & 7;
    const int m0 = mt * 128, nb = nt * 128;
    const int ip = t & 1;
    const __half* __restrict__ hin = g_h[ip];
    __half* __restrict__ hout = g_h[ip ^ 1];

    uint32_t sb = smem_u32(smem);
    float* bias_s = (float*)(smem + S_BIAS);
    if (tid < 128) bias_s[tid] = g_bias[nb + tid];

    const __half* xh = g_x72 + (size_t)t * BATCH * XCOLS;

    // ---- stage 0 is h-independent: issue before the dependency spin ----
    load_stage(sb, m0, nb, 0, tid, xh, hin);
    CP_COMMIT();

    // ---- dependency wait: h_{t-1}[m-rows] produced by the 8 (t-1, mt, *) tiles ----
    if (t > 0) {
        if (tid == 0) {
            while (atomicAdd(&g_cnt[(t - 1) * MTILES + mt], 0u) < 8u)
                __nanosleep(64);
            __threadfence();
        }
        __syncthreads();
    }

    // tail (h-dependent) joins the next commit group (with stage 1)
    load_tail(sb, m0, nb, tid, hin);

    float acc[64];
    #pragma unroll
    for (int i = 0; i < 64; i++) acc[i] = 0.f;

    // warp tile: 32 (M) x 64 (N); 8 warps = 4M x 2N
    const int mwarp = (w >> 1) * 32, nwarp = (w & 1) * 64;
    const int laneA_row = (lane & 7) + ((lane >> 3) & 1) * 8;
    const uint32_t laneA_col = (uint32_t)((lane >> 4) * 16);
    const int laneB_row = (lane & 7) + ((lane >> 4) << 3);
    const uint32_t laneB_col = (uint32_t)(((lane >> 3) & 1) * 16);

    #pragma unroll 1
    for (int s = 0; s < NSTAGE; s++) {
        if (s + 1 < NSTAGE) {
            load_stage(sb, m0, nb, s + 1, tid, xh, hin);
            CP_COMMIT();
            CP_WAIT1();
        } else {
            CP_WAIT0();
        }
        __syncthreads();

        const uint32_t base = sb + (uint32_t)(s & 1) * STG_BYTES;
        #pragma unroll
        for (int kk = 0; kk < 4; kk++) {
            uint32_t af[2][4];
            #pragma unroll
            for (int mm = 0; mm < 2; mm++) {
                int rA = mwarp + mm * 16 + laneA_row;
                uint32_t ca = ((uint32_t)(kk * 32) + laneA_col) ^ (uint32_t)((rA & 7) * 16);
                ldsm4(af[mm], base + S_A + (uint32_t)(rA * 128) + ca);
            }
            #pragma unroll
            for (int bn = 0; bn < 4; bn++) {
                int rB = nwarp + bn * 16 + laneB_row;
                uint32_t cb = ((uint32_t)(kk * 32) + laneB_col) ^ (uint32_t)((rB & 7) * 16);
                uint32_t bh[4], bl[4];
                ldsm4(bh, base + S_B_HI + (uint32_t)(rB * 128) + cb);
                ldsm4(bl, base + S_B_LO + (uint32_t)(rB * 128) + cb);
                #pragma unroll
                for (int mm = 0; mm < 2; mm++) {
                    float* a0 = acc + (mm * 8 + bn * 2) * 4;
                    float* a1 = a0 + 4;
                    mma16816(a0, af[mm], bh[0], bh[1]);
                    mma16816(a0, af[mm], bl[0], bl[1]);
                    mma16816(a1, af[mm], bh[2], bh[3]);
                    mma16816(a1, af[mm], bl[2], bl[3]);
                }
            }
        }
        __syncthreads();
    }

    // ---- tail K8 pass (k 320..327) ----
    {
        const int lrow = lane & 15;
        #pragma unroll
        for (int mm = 0; mm < 2; mm++) {
            int rA = mwarp + mm * 16 + lrow;
            uint32_t a2[2];
            ldsm2(a2, sb + S_TAIL + T_A + (uint32_t)(rA * 16));
            uint32_t aT[4] = {a2[0], a2[1], 0u, 0u};
            #pragma unroll
            for (int bn = 0; bn < 4; bn++) {
                int rB = nwarp + bn * 16 + lrow;
                uint32_t b2h[2], b2l[2];
                ldsm2(b2h, sb + S_TAIL + T_B_HI + (uint32_t)(rB * 16));
                ldsm2(b2l, sb + S_TAIL + T_B_LO + (uint32_t)(rB * 16));
                float* a0 = acc + (mm * 8 + bn * 2) * 4;
                float* a1 = a0 + 4;
                mma16816(a0, aT, b2h[0], 0u);
                mma16816(a0, aT, b2l[0], 0u);
                mma16816(a1, aT, b2h[1], 0u);
                mma16816(a1, aT, b2l[1], 0u);
            }
        }
    }

    // ---- fused LSTM epilogue ----
    const int c = 2 * (lane & 3);
    #pragma unroll
    for (int mm = 0; mm < 2; mm++) {
        #pragma unroll
        for (int rs = 0; rs < 2; rs++) {
            const int row = m0 + mwarp + mm * 16 + (lane >> 2) + rs * 8;
            #pragma unroll
            for (int h8 = 0; h8 < 2; h8++) {
                const int u = h8 * 8 + c;
                const int bcol = nwarp + u;
                float i0 = acc[(mm * 8 + 0 + h8) * 4 + rs * 2 + 0] + bias_s[bcol];
                float i1 = acc[(mm * 8 + 0 + h8) * 4 + rs * 2 + 1] + bias_s[bcol + 1];
                float f0 = acc[(mm * 8 + 2 + h8) * 4 + rs * 2 + 0] + bias_s[bcol + 16];
                float f1 = acc[(mm * 8 + 2 + h8) * 4 + rs * 2 + 1] + bias_s[bcol + 17];
                float g0 = acc[(mm * 8 + 4 + h8) * 4 + rs * 2 + 0] + bias_s[bcol + 32];
                float g1 = acc[(mm * 8 + 4 + h8) * 4 + rs * 2 + 1] + bias_s[bcol + 33];
                float o0 = acc[(mm * 8 + 6 + h8) * 4 + rs * 2 + 0] + bias_s[bcol + 48];
                float o1 = acc[(mm * 8 + 6 + h8) * 4 + rs * 2 + 1] + bias_s[bcol + 49];
                size_t cix = (size_t)row * HIDDEN + nt * 32 + (w & 1) * 16 + u;
                float2 cv = *reinterpret_cast<float2*>(g_c + cix);
                float nc0 = sigm(f0) * cv.x + sigm(i0) * tanhf_(g0);
                float nc1 = sigm(f1) * cv.y + sigm(i1) * tanhf_(g1);
                *reinterpret_cast<float2*>(g_c + cix) = make_float2(nc0, nc1);
                float h0 = sigm(o0) * tanhf_(nc0);
                float h1 = sigm(o1) * tanhf_(nc1);
                *reinterpret_cast<__half2*>(hout + cix) = __floats2half2_rn(h0, h1);
            }
        }
    }

    // ---- signal: this (t, mt) tile done ----
    __syncthreads();
    if (tid == 0) {
        __threadfence();
        atomicAdd(&g_cnt[t * MTILES + mt], 1u);
    }
}

// ---------------- MLP heads ----------------
static constexpr int H_W1M = 0, H_W2M = 16384, H_W3M = 20480;
static constexpr int H_W1L = 21504, H_W2L = 29696, H_W3L = 30720;
static constexpr int H_B1M = 31232, H_B2M = 31296, H_B3M = 31360;
static constexpr int H_B1L = 31376, H_B2L = 31408, H_B3L = 31440;
static constexpr int HEADS_SMEM = 31456 * 4;

__global__ __launch_bounds__(128, 1)
void heads_kernel(const float* __restrict__ mW1, const float* __restrict__ mb1,
                  const float* __restrict__ mW2, const float* __restrict__ mb2,
                  const float* __restrict__ mW3, const float* __restrict__ mb3,
                  const float* __restrict__ lW1, const float* __restrict__ lb1,
                  const float* __restrict__ lW2, const float* __restrict__ lb2,
                  const float* __restrict__ lW3, const float* __restrict__ lb3,
                  float* __restrict__ out) {
    extern __shared__ float sw[];
    const int tid = threadIdx.x;
    for (int i = tid; i < 16384; i += 128) sw[H_W1M + i] = mW1[i];
    for (int i = tid; i < 4096;  i += 128) sw[H_W2M + i] = mW2[i];
    for (int i = tid; i < 1024;  i += 128) sw[H_W3M + i] = mW3[i];
    for (int i = tid; i < 8192;  i += 128) sw[H_W1L + i] = lW1[i];
    for (int i = tid; i < 1024;  i += 128) sw[H_W2L + i] = lW2[i];
    for (int i = tid; i < 512;   i += 128) sw[H_W3L + i] = lW3[i];
    if (tid < 64) { sw[H_B1M + tid] = mb1[tid]; sw[H_B2M + tid] = mb2[tid]; }
    if (tid < 32) { sw[H_B1L + tid] = lb1[tid]; sw[H_B2L + tid] = lb2[tid]; }
    if (tid < 16) { sw[H_B3M + tid] = mb3[tid]; sw[H_B3L + tid] = lb3[tid]; }
    __syncthreads();

    const int row = blockIdx.x * 128 + tid;
    const __half* hh = g_h[0];   // T=50 even -> final h parity 0
    const size_t hbase = (size_t)row * HIDDEN;

    float x1[64], y1[32];
    #pragma unroll
    for (int j = 0; j < 64; j++) x1[j] = sw[H_B1M + j];
    #pragma unroll
    for (int j = 0; j < 32; j++) y1[j] = sw[H_B1L + j];

    for (int kc = 0; kc < 16; kc++) {
        float hk[16];
        #pragma unroll
        for (int n = 0; n < 16; n++) hk[n] = __half2float(hh[hbase + kc * 16 + n]);
        #pragma unroll
        for (int n = 0; n < 16; n++) {
            const int k = kc * 16 + n;
            #pragma unroll
            for (int j4 = 0; j4 < 16; j4++) {
                float4 wv = *reinterpret_cast<const float4*>(sw + H_W1M + k * 64 + j4 * 4);
                x1[j4*4+0] += hk[n] * wv.x; x1[j4*4+1] += hk[n] * wv.y;
                x1[j4*4+2] += hk[n] * wv.z; x1[j4*4+3] += hk[n] * wv.w;
            }
            #pragma unroll
            for (int j4 = 0; j4 < 8; j4++) {
                float4 wv = *reinterpret_cast<const float4*>(sw + H_W1L + k * 32 + j4 * 4);
                y1[j4*4+0] += hk[n] * wv.x; y1[j4*4+1] += hk[n] * wv.y;
                y1[j4*4+2] += hk[n] * wv.z; y1[j4*4+3] += hk[n] * wv.w;
            }
        }
    }

    float x2[64];
    #pragma unroll
    for (int j = 0; j < 64; j++) { x1[j] = fmaxf(x1[j], 0.f); x2[j] = sw[H_B2M + j]; }
    #pragma unroll
    for (int k = 0; k < 64; k++) {
        #pragma unroll
        for (int j4 = 0; j4 < 16; j4++) {
            float4 wv = *reinterpret_cast<const float4*>(sw + H_W2M + k * 64 + j4 * 4);
            x2[j4*4+0] += x1[k] * wv.x; x2[j4*4+1] += x1[k] * wv.y;
            x2[j4*4+2] += x1[k] * wv.z; x2[j4*4+3] += x1[k] * wv.w;
        }
    }
    float mu[16];
    #pragma unroll
    for (int j = 0; j < 16; j++) mu[j] = sw[H_B3M + j];
    #pragma unroll
    for (int k = 0; k < 64; k++) {
        float xv = fmaxf(x2[k], 0.f);
        #pragma unroll
        for (int j4 = 0; j4 < 4; j4++) {
            float4 wv = *reinterpret_cast<const float4*>(sw + H_W3M + k * 16 + j4 * 4);
            mu[j4*4+0] += xv * wv.x; mu[j4*4+1] += xv * wv.y;
            mu[j4*4+2] += xv * wv.z; mu[j4*4+3] += xv * wv.w;
        }
    }
    #pragma unroll
    for (int j4 = 0; j4 < 4; j4++)
        *reinterpret_cast<float4*>(out + (size_t)row * 16 + j4 * 4) =
            make_float4(mu[j4*4], mu[j4*4+1], mu[j4*4+2], mu[j4*4+3]);

    float y2[32];
    #pragma unroll
    for (int j = 0; j < 32; j++) { y1[j] = fmaxf(y1[j], 0.f); y2[j] = sw[H_B2L + j]; }
    #pragma unroll
    for (int k = 0; k < 32; k++) {
        #pragma unroll
        for (int j4 = 0; j4 < 8; j4++) {
            float4 wv = *reinterpret_cast<const float4*>(sw + H_W2L + k * 32 + j4 * 4);
            y2[j4*4+0] += y1[k] * wv.x; y2[j4*4+1] += y1[k] * wv.y;
            y2[j4*4+2] += y1[k] * wv.z; y2[j4*4+3] += y1[k] * wv.w;
        }
    }
    float ls[16];
    #pragma unroll
    for (int j = 0; j < 16; j++) ls[j] = sw[H_B3L + j];
    #pragma unroll
    for (int k = 0; k < 32; k++) {
        float xv = fmaxf(y2[k], 0.f);
        #pragma unroll
        for (int j4 = 0; j4 < 4; j4++) {
            float4 wv = *reinterpret_cast<const float4*>(sw + H_W3L + k * 16 + j4 * 4);
            ls[j4*4+0] += xv * wv.x; ls[j4*4+1] += xv * wv.y;
            ls[j4*4+2] += xv * wv.z; ls[j4*4+3] += xv * wv.w;
        }
    }
    float* sig = out + (size_t)BATCH * 16 + (size_t)row * 16;
    #pragma unroll
    for (int j = 0; j < 16; j++)
        sig[j] = __expf(fminf(fmaxf(ls[j], -10.f), 2.f));
}

// ---------------- launch ----------------
extern "C" void kernel_launch(void* const* d_in, const int* in_sizes, int n_in,
                              void* d_out, int out_size) {
    const float* obs = (const float*)d_in[0];
    const float* act = (const float*)d_in[1];
    const float* Wi  = (const float*)d_in[2];
    const float* Wh  = (const float*)d_in[3];
    const float* b   = (const float*)d_in[4];
    const float* mW1 = (const float*)d_in[5],  *mb1 = (const float*)d_in[6];
    const float* mW2 = (const float*)d_in[7],  *mb2 = (const float*)d_in[8];
    const float* mW3 = (const float*)d_in[9],  *mb3 = (const float*)d_in[10];
    const float* lW1 = (const float*)d_in[11], *lb1 = (const float*)d_in[12];
    const float* lW2 = (const float*)d_in[13], *lb2 = (const float*)d_in[14];
    const float* lW3 = (const float*)d_in[15], *lb3 = (const float*)d_in[16];
    float* out = (float*)d_out;

    cudaFuncSetAttribute(lstm_stream_kernel,
                         cudaFuncAttributeMaxDynamicSharedMemorySize, STEP_SMEM);
    cudaFuncSetAttribute(heads_kernel,
                         cudaFuncAttributeMaxDynamicSharedMemorySize, HEADS_SMEM);

    zero_state_kernel<<<512, 256>>>();
    prep_weights_kernel<<<384, 256>>>(Wi, Wh, b);
    prep_x_kernel<<<4096, 256>>>(obs, act);
    lstm_stream_kernel<<<TSTEPS * TILES_PER_STEP, 256, STEP_SMEM>>>();
    heads_kernel<<<BATCH / 128, 128, HEADS_SMEM>>>(mW1, mb1, mW2, mb2, mW3, mb3,
                                                   lW1, lb1, lW2, lb2, lW3, lb3, out);
}

// round 15
// speedup vs baseline: 1.0656x; 1.0098x over previous
#include <cuda_runtime.h>
#include <cuda_fp16.h>
#include <cstdint>

#define BATCH  16384
#define TSTEPS 50
#define HIDDEN 256
#define XCOLS  72       // obs64 | act8, unpadded
#define NSTAGE 5        // 5 x K64 covers k[0,320); tail K8 covers k[320,328)
#define NGATE  1024
#define KTOT   328      // x[0,72) | h[72,328)
#define MTILES 128
#define NTILES 8
#define TILES_PER_STEP (MTILES * NTILES)   // 1024

// ---------------- device scratch ----------------
__device__ __align__(16) __half g_Wb_hi[NGATE * KTOT];
__device__ __align__(16) __half g_Wb_lo[NGATE * KTOT];
__device__ float g_bias[NGATE];
__device__ __align__(16) float  g_c[BATCH * HIDDEN];
__device__ __align__(16) __half g_h[2][BATCH * HIDDEN];
__device__ __align__(16) __half g_x72[(size_t)TSTEPS * BATCH * XCOLS];
__device__ unsigned int g_cnt[TSTEPS * MTILES];   // n-tiles done per (t, mtile)

// ---------------- helpers ----------------
__device__ __forceinline__ uint32_t smem_u32(const void* p) {
    uint32_t a;
    asm("{ .reg .u64 t; cvta.to.shared.u64 t, %1; cvt.u32.u64 %0, t; }" : "=r"(a) : "l"(p));
    return a;
}
__device__ __forceinline__ void cpasync16(uint32_t dst, const void* src) {
    asm volatile("cp.async.cg.shared.global [%0], [%1], 16;" :: "r"(dst), "l"(src));
}
#define CP_COMMIT() asm volatile("cp.async.commit_group;" ::: "memory")
#define CP_WAIT1()  asm volatile("cp.async.wait_group 1;" ::: "memory")
#define CP_WAIT0()  asm volatile("cp.async.wait_group 0;" ::: "memory")

__device__ __forceinline__ void ldsm4(uint32_t* r, uint32_t addr) {
    asm volatile("ldmatrix.sync.aligned.m8n8.x4.shared.b16 {%0,%1,%2,%3}, [%4];"
                 : "=r"(r[0]), "=r"(r[1]), "=r"(r[2]), "=r"(r[3]) : "r"(addr));
}
__device__ __forceinline__ void ldsm2(uint32_t* r, uint32_t addr) {
    asm volatile("ldmatrix.sync.aligned.m8n8.x2.shared.b16 {%0,%1}, [%2];"
                 : "=r"(r[0]), "=r"(r[1]) : "r"(addr));
}
__device__ __forceinline__ void mma16816(float* d, const uint32_t* a, uint32_t b0, uint32_t b1) {
    asm volatile("mma.sync.aligned.m16n8k16.row.col.f32.f16.f16.f32 "
                 "{%0,%1,%2,%3}, {%4,%5,%6,%7}, {%8,%9}, {%0,%1,%2,%3};"
                 : "+f"(d[0]), "+f"(d[1]), "+f"(d[2]), "+f"(d[3])
                 : "r"(a[0]), "r"(a[1]), "r"(a[2]), "r"(a[3]), "r"(b0), "r"(b1));
}
__device__ __forceinline__ float sigm(float x)   { return 1.f / (1.f + __expf(-x)); }
__device__ __forceinline__ float tanhf_(float x) { return 1.f - 2.f / (__expf(2.f * x) + 1.f); }

// ---------------- init kernels ----------------
__global__ void zero_state_kernel() {
    size_t i0 = (size_t)blockIdx.x * blockDim.x + threadIdx.x;
    size_t st = (size_t)gridDim.x * blockDim.x;
    const __half z = __float2half(0.f);
    for (size_t i = i0; i < (size_t)BATCH * HIDDEN; i += st) {
        g_c[i] = 0.f; g_h[0][i] = z;
    }
    for (size_t i = i0; i < TSTEPS * MTILES; i += st) g_cnt[i] = 0u;
}

// Column permutation for warp tile 32x64 over N-tile 128:
// n = nb8*128 + hf*64 + gate*16 + u  ->  orig col gate*256 + nb8*32 + hf*16 + u
// K layout: k<72 -> x (obs|act), k in [72,328) -> h
__global__ void prep_weights_kernel(const float* __restrict__ Wi, const float* __restrict__ Wh,
                                    const float* __restrict__ bias) {
    int i0 = blockIdx.x * blockDim.x + threadIdx.x;
    int st = gridDim.x * blockDim.x;
    for (int idx = i0; idx < NGATE * KTOT; idx += st) {
        int n = idx / KTOT, k = idx - n * KTOT;
        int nb8 = n >> 7, rem = n & 127, hf = rem >> 6, ncol = rem & 63;
        int gate = ncol >> 4, u = ncol & 15;
        int src = gate * 256 + nb8 * 32 + hf * 16 + u;
        float w = (k < 72) ? Wi[k * NGATE + src] : Wh[(k - 72) * NGATE + src];
        __half hi = __float2half_rn(w);
        g_Wb_hi[n * KTOT + k] = hi;
        g_Wb_lo[n * KTOT + k] = __float2half_rn(w - __half2float(hi));
    }
    if (i0 < NGATE) {
        int nb8 = i0 >> 7, rem = i0 & 127, hf = rem >> 6, ncol = rem & 63;
        int gate = ncol >> 4, u = ncol & 15;
        g_bias[i0] = bias[gate * 256 + nb8 * 32 + hf * 16 + u];
    }
}

// g_x72: [t][b][72], obs 0..63 | act 64..71
__global__ void prep_x_kernel(const float* __restrict__ obs, const float* __restrict__ act) {
    size_t i0 = (size_t)blockIdx.x * blockDim.x + threadIdx.x;
    size_t st = (size_t)gridDim.x * blockDim.x;
    const size_t N = (size_t)TSTEPS * BATCH * XCOLS;
    for (size_t i = i0; i < N; i += st) {
        int col = (int)(i % XCOLS);
        size_t m = i / XCOLS;
        int b = (int)(m & (BATCH - 1));
        int t = (int)(m >> 14);
        float v = (col < 64) ? obs[((size_t)b * TSTEPS + t) * 64 + col]
                             : act[((size_t)b * TSTEPS + t) * 8 + (col - 64)];
        g_x72[i] = __float2half_rn(v);
    }
}

// ---------------- streamed LSTM tile kernel ----------------
static constexpr int STG_BYTES = 49152;
static constexpr int S_A    = 0;
static constexpr int S_B_HI = 16384;
static constexpr int S_B_LO = 32768;
static constexpr int S_TAIL = 2 * STG_BYTES;          // 98304
static constexpr int T_A    = 0, T_B_HI = 2048, T_B_LO = 4096;
static constexpr int S_BIAS = S_TAIL + 6144;          // 104448
static constexpr int STEP_SMEM = S_BIAS + 512;        // 104960

// stage s covers k [s*64, s*64+64): k<72 -> x72, else h (k-72)
// with_lo = 0 skips the B_lo tile (stage 0: obs columns, lo-term dropped)
__device__ __forceinline__ void load_stage(
    uint32_t sb, int m0, int nb, int s, int tid, int with_lo,
    const __half* __restrict__ xh, const __half* __restrict__ hin)
{
    const uint32_t base = sb + (uint32_t)(s & 1) * STG_BYTES;
    #pragma unroll
    for (int it = 0; it < 4; it++) {
        int q = tid + it * 256;                 // 1024 quads: 128 rows x 8
        int r = q >> 3, c = q & 7;
        int k = s * 64 + c * 8;
        uint32_t d = (uint32_t)(r * 128) + (uint32_t)((c * 16) ^ ((r & 7) * 16));
        const __half* sa = (k < 72)
            ? xh  + (size_t)(m0 + r) * XCOLS + k
            : hin + (size_t)(m0 + r) * HIDDEN + (k - 72);
        cpasync16(base + S_A + d, sa);
        size_t ob = (size_t)(nb + r) * KTOT + k;
        cpasync16(base + S_B_HI + d, g_Wb_hi + ob);
        if (with_lo) cpasync16(base + S_B_LO + d, g_Wb_lo + ob);
    }
}

// tail: k [320, 328), 128 rows x 8 cols, 16B rows, no swizzle (h-dependent)
__device__ __forceinline__ void load_tail(
    uint32_t sb, int m0, int nb, int tid, const __half* __restrict__ hin)
{
    if (tid < 128) {
        int r = tid;
        cpasync16(sb + S_TAIL + T_A + (uint32_t)(r * 16),
                  hin + (size_t)(m0 + r) * HIDDEN + (320 - 72));
        size_t ob = (size_t)(nb + r) * KTOT + 320;
        cpasync16(sb + S_TAIL + T_B_HI + (uint32_t)(r * 16), g_Wb_hi + ob);
        cpasync16(sb + S_TAIL + T_B_LO + (uint32_t)(r * 16), g_Wb_lo + ob);
    }
}

__global__ __launch_bounds__(256, 2)
void lstm_stream_kernel() {
    extern __shared__ char smem[];
    const int tid = threadIdx.x, w = tid >> 5, lane = tid & 31;
    const int bid = blockIdx.x;
    const int t = bid >> 10;                   // bid / 1024
    const int tile = bid & (TILES_PER_STEP - 1);
    const int mt = tile >> 3, nt = tile & 7;
    const int m0 = mt * 128, nb = nt * 128;
    const int ip = t & 1;
    const __half* __restrict__ hin = g_h[ip];
    __half* __restrict__ hout = g_h[ip ^ 1];

    uint32_t sb = smem_u32(smem);
    float* bias_s = (float*)(smem + S_BIAS);
    if (tid < 128) bias_s[tid] = g_bias[nb + tid];

    const __half* xh = g_x72 + (size_t)t * BATCH * XCOLS;

    // ---- stage 0 (pure-x, hi-only): h-independent, issue before the spin ----
    load_stage(sb, m0, nb, 0, tid, /*with_lo=*/0, xh, hin);
    CP_COMMIT();

    // ---- dependency wait: h_{t-1}/c_{t-1}[m-rows] from the 8 (t-1, mt, *) tiles ----
    if (t > 0) {
        if (tid == 0) {
            while (atomicAdd(&g_cnt[(t - 1) * MTILES + mt], 0u) < 8u)
                __nanosleep(64);
            __threadfence();
        }
        __syncthreads();
    }

    // tail (h-dependent) joins the next commit group (with stage 1)
    load_tail(sb, m0, nb, tid, hin);

    // L2-prefetch this tile's c lines (128 rows x 32 floats = 1 line/row)
    if (tid < 128) {
        const float* cp = g_c + (size_t)(m0 + tid) * HIDDEN + nt * 32;
        asm volatile("prefetch.global.L2 [%0];" :: "l"(cp));
    }

    float acc[64];
    #pragma unroll
    for (int i = 0; i < 64; i++) acc[i] = 0.f;

    // warp tile: 32 (M) x 64 (N); 8 warps = 4M x 2N
    const int mwarp = (w >> 1) * 32, nwarp = (w & 1) * 64;
    const int laneA_row = (lane & 7) + ((lane >> 3) & 1) * 8;
    const uint32_t laneA_col = (uint32_t)((lane >> 4) * 16);
    const int laneB_row = (lane & 7) + ((lane >> 4) << 3);
    const uint32_t laneB_col = (uint32_t)(((lane >> 3) & 1) * 16);

    #pragma unroll 1
    for (int s = 0; s < NSTAGE; s++) {
        if (s + 1 < NSTAGE) {
            load_stage(sb, m0, nb, s + 1, tid, /*with_lo=*/1, xh, hin);
            CP_COMMIT();
            CP_WAIT1();
        } else {
            CP_WAIT0();
        }
        __syncthreads();

        const uint32_t base = sb + (uint32_t)(s & 1) * STG_BYTES;
        #pragma unroll
        for (int kk = 0; kk < 4; kk++) {
            uint32_t af[2][4];
            #pragma unroll
            for (int mm = 0; mm < 2; mm++) {
                int rA = mwarp + mm * 16 + laneA_row;
                uint32_t ca = ((uint32_t)(kk * 32) + laneA_col) ^ (uint32_t)((rA & 7) * 16);
                ldsm4(af[mm], base + S_A + (uint32_t)(rA * 128) + ca);
            }
            #pragma unroll
            for (int bn = 0; bn < 4; bn++) {
                int rB = nwarp + bn * 16 + laneB_row;
                uint32_t cb = ((uint32_t)(kk * 32) + laneB_col) ^ (uint32_t)((rB & 7) * 16);
                uint32_t bh[4];
                ldsm4(bh, base + S_B_HI + (uint32_t)(rB * 128) + cb);
                if (s != 0) {
                    uint32_t bl[4];
                    ldsm4(bl, base + S_B_LO + (uint32_t)(rB * 128) + cb);
                    #pragma unroll
                    for (int mm = 0; mm < 2; mm++) {
                        float* a0 = acc + (mm * 8 + bn * 2) * 4;
                        float* a1 = a0 + 4;
                        mma16816(a0, af[mm], bh[0], bh[1]);
                        mma16816(a0, af[mm], bl[0], bl[1]);
                        mma16816(a1, af[mm], bh[2], bh[3]);
                        mma16816(a1, af[mm], bl[2], bl[3]);
                    }
                } else {
                    #pragma unroll
                    for (int mm = 0; mm < 2; mm++) {
                        float* a0 = acc + (mm * 8 + bn * 2) * 4;
                        float* a1 = a0 + 4;
                        mma16816(a0, af[mm], bh[0], bh[1]);
                        mma16816(a1, af[mm], bh[2], bh[3]);
                    }
                }
            }
        }
        __syncthreads();
    }

    // ---- tail K8 pass (k 320..327) ----
    {
        const int lrow = lane & 15;
        #pragma unroll
        for (int mm = 0; mm < 2; mm++) {
            int rA = mwarp + mm * 16 + lrow;
            uint32_t a2[2];
            ldsm2(a2, sb + S_TAIL + T_A + (uint32_t)(rA * 16));
            uint32_t aT[4] = {a2[0], a2[1], 0u, 0u};
            #pragma unroll
            for (int bn = 0; bn < 4; bn++) {
                int rB = nwarp + bn * 16 + lrow;
                uint32_t b2h[2], b2l[2];
                ldsm2(b2h, sb + S_TAIL + T_B_HI + (uint32_t)(rB * 16));
                ldsm2(b2l, sb + S_TAIL + T_B_LO + (uint32_t)(rB * 16));
                float* a0 = acc + (mm * 8 + bn * 2) * 4;
                float* a1 = a0 + 4;
                mma16816(a0, aT, b2h[0], 0u);
                mma16816(a0, aT, b2l[0], 0u);
                mma16816(a1, aT, b2h[1], 0u);
                mma16816(a1, aT, b2l[1], 0u);
            }
        }
    }

    // ---- fused LSTM epilogue ----
    const int c = 2 * (lane & 3);
    #pragma unroll
    for (int mm = 0; mm < 2; mm++) {
        #pragma unroll
        for (int rs = 0; rs < 2; rs++) {
            const int row = m0 + mwarp + mm * 16 + (lane >> 2) + rs * 8;
            #pragma unroll
            for (int h8 = 0; h8 < 2; h8++) {
                const int u = h8 * 8 + c;
                const int bcol = nwarp + u;
                float i0 = acc[(mm * 8 + 0 + h8) * 4 + rs * 2 + 0] + bias_s[bcol];
                float i1 = acc[(mm * 8 + 0 + h8) * 4 + rs * 2 + 1] + bias_s[bcol + 1];
                float f0 = acc[(mm * 8 + 2 + h8) * 4 + rs * 2 + 0] + bias_s[bcol + 16];
                float f1 = acc[(mm * 8 + 2 + h8) * 4 + rs * 2 + 1] + bias_s[bcol + 17];
                float g0 = acc[(mm * 8 + 4 + h8) * 4 + rs * 2 + 0] + bias_s[bcol + 32];
                float g1 = acc[(mm * 8 + 4 + h8) * 4 + rs * 2 + 1] + bias_s[bcol + 33];
                float o0 = acc[(mm * 8 + 6 + h8) * 4 + rs * 2 + 0] + bias_s[bcol + 48];
                float o1 = acc[(mm * 8 + 6 + h8) * 4 + rs * 2 + 1] + bias_s[bcol + 49];
                size_t cix = (size_t)row * HIDDEN + nt * 32 + (w & 1) * 16 + u;
                float2 cv = *reinterpret_cast<float2*>(g_c + cix);
                float nc0 = sigm(f0) * cv.x + sigm(i0) * tanhf_(g0);
                float nc1 = sigm(f1) * cv.y + sigm(i1) * tanhf_(g1);
                *reinterpret_cast<float2*>(g_c + cix) = make_float2(nc0, nc1);
                float h0 = sigm(o0) * tanhf_(nc0);
                float h1 = sigm(o1) * tanhf_(nc1);
                *reinterpret_cast<__half2*>(hout + cix) = __floats2half2_rn(h0, h1);
            }
        }
    }

    // ---- signal: this (t, mt) tile done ----
    __syncthreads();
    if (tid == 0) {
        __threadfence();
        atomicAdd(&g_cnt[t * MTILES + mt], 1u);
    }
}

// ---------------- MLP heads ----------------
static constexpr int H_W1M = 0, H_W2M = 16384, H_W3M = 20480;
static constexpr int H_W1L = 21504, H_W2L = 29696, H_W3L = 30720;
static constexpr int H_B1M = 31232, H_B2M = 31296, H_B3M = 31360;
static constexpr int H_B1L = 31376, H_B2L = 31408, H_B3L = 31440;
static constexpr int HEADS_SMEM = 31456 * 4;

__global__ __launch_bounds__(128, 1)
void heads_kernel(const float* __restrict__ mW1, const float* __restrict__ mb1,
                  const float* __restrict__ mW2, const float* __restrict__ mb2,
                  const float* __restrict__ mW3, const float* __restrict__ mb3,
                  const float* __restrict__ lW1, const float* __restrict__ lb1,
                  const float* __restrict__ lW2, const float* __restrict__ lb2,
                  const float* __restrict__ lW3, const float* __restrict__ lb3,
                  float* __restrict__ out) {
    extern __shared__ float sw[];
    const int tid = threadIdx.x;
    for (int i = tid; i < 16384; i += 128) sw[H_W1M + i] = mW1[i];
    for (int i = tid; i < 4096;  i += 128) sw[H_W2M + i] = mW2[i];
    for (int i = tid; i < 1024;  i += 128) sw[H_W3M + i] = mW3[i];
    for (int i = tid; i < 8192;  i += 128) sw[H_W1L + i] = lW1[i];
    for (int i = tid; i < 1024;  i += 128) sw[H_W2L + i] = lW2[i];
    for (int i = tid; i < 512;   i += 128) sw[H_W3L + i] = lW3[i];
    if (tid < 64) { sw[H_B1M + tid] = mb1[tid]; sw[H_B2M + tid] = mb2[tid]; }
    if (tid < 32) { sw[H_B1L + tid] = lb1[tid]; sw[H_B2L + tid] = lb2[tid]; }
    if (tid < 16) { sw[H_B3M + tid] = mb3[tid]; sw[H_B3L + tid] = lb3[tid]; }
    __syncthreads();

    const int row = blockIdx.x * 128 + tid;
    const __half* hh = g_h[0];   // T=50 even -> final h parity 0
    const size_t hbase = (size_t)row * HIDDEN;

    float x1[64], y1[32];
    #pragma unroll
    for (int j = 0; j < 64; j++) x1[j] = sw[H_B1M + j];
    #pragma unroll
    for (int j = 0; j < 32; j++) y1[j] = sw[H_B1L + j];

    for (int kc = 0; kc < 16; kc++) {
        float hk[16];
        #pragma unroll
        for (int n = 0; n < 16; n++) hk[n] = __half2float(hh[hbase + kc * 16 + n]);
        #pragma unroll
        for (int n = 0; n < 16; n++) {
            const int k = kc * 16 + n;
            #pragma unroll
            for (int j4 = 0; j4 < 16; j4++) {
                float4 wv = *reinterpret_cast<const float4*>(sw + H_W1M + k * 64 + j4 * 4);
                x1[j4*4+0] += hk[n] * wv.x; x1[j4*4+1] += hk[n] * wv.y;
                x1[j4*4+2] += hk[n] * wv.z; x1[j4*4+3] += hk[n] * wv.w;
            }
            #pragma unroll
            for (int j4 = 0; j4 < 8; j4++) {
                float4 wv = *reinterpret_cast<const float4*>(sw + H_W1L + k * 32 + j4 * 4);
                y1[j4*4+0] += hk[n] * wv.x; y1[j4*4+1] += hk[n] * wv.y;
                y1[j4*4+2] += hk[n] * wv.z; y1[j4*4+3] += hk[n] * wv.w;
            }
        }
    }

    float x2[64];
    #pragma unroll
    for (int j = 0; j < 64; j++) { x1[j] = fmaxf(x1[j], 0.f); x2[j] = sw[H_B2M + j]; }
    #pragma unroll
    for (int k = 0; k < 64; k++) {
        #pragma unroll
        for (int j4 = 0; j4 < 16; j4++) {
            float4 wv = *reinterpret_cast<const float4*>(sw + H_W2M + k * 64 + j4 * 4);
            x2[j4*4+0] += x1[k] * wv.x; x2[j4*4+1] += x1[k] * wv.y;
            x2[j4*4+2] += x1[k] * wv.z; x2[j4*4+3] += x1[k] * wv.w;
        }
    }
    float mu[16];
    #pragma unroll
    for (int j = 0; j < 16; j++) mu[j] = sw[H_B3M + j];
    #pragma unroll
    for (int k = 0; k < 64; k++) {
        float xv = fmaxf(x2[k], 0.f);
        #pragma unroll
        for (int j4 = 0; j4 < 4; j4++) {
            float4 wv = *reinterpret_cast<const float4*>(sw + H_W3M + k * 16 + j4 * 4);
            mu[j4*4+0] += xv * wv.x; mu[j4*4+1] += xv * wv.y;
            mu[j4*4+2] += xv * wv.z; mu[j4*4+3] += xv * wv.w;
        }
    }
    #pragma unroll
    for (int j4 = 0; j4 < 4; j4++)
        *reinterpret_cast<float4*>(out + (size_t)row * 16 + j4 * 4) =
            make_float4(mu[j4*4], mu[j4*4+1], mu[j4*4+2], mu[j4*4+3]);

    float y2[32];
    #pragma unroll
    for (int j = 0; j < 32; j++) { y1[j] = fmaxf(y1[j], 0.f); y2[j] = sw[H_B2L + j]; }
    #pragma unroll
    for (int k = 0; k < 32; k++) {
        #pragma unroll
        for (int j4 = 0; j4 < 8; j4++) {
            float4 wv = *reinterpret_cast<const float4*>(sw + H_W2L + k * 32 + j4 * 4);
            y2[j4*4+0] += y1[k] * wv.x; y2[j4*4+1] += y1[k] * wv.y;
            y2[j4*4+2] += y1[k] * wv.z; y2[j4*4+3] += y1[k] * wv.w;
        }
    }
    float ls[16];
    #pragma unroll
    for (int j = 0; j < 16; j++) ls[j] = sw[H_B3L + j];
    #pragma unroll
    for (int k = 0; k < 32; k++) {
        float xv = fmaxf(y2[k], 0.f);
        #pragma unroll
        for (int j4 = 0; j4 < 4; j4++) {
            float4 wv = *reinterpret_cast<const float4*>(sw + H_W3L + k * 16 + j4 * 4);
            ls[j4*4+0] += xv * wv.x; ls[j4*4+1] += xv * wv.y;
            ls[j4*4+2] += xv * wv.z; ls[j4*4+3] += xv * wv.w;
        }
    }
    float* sig = out + (size_t)BATCH * 16 + (size_t)row * 16;
    #pragma unroll
    for (int j = 0; j < 16; j++)
        sig[j] = __expf(fminf(fmaxf(ls[j], -10.f), 2.f));
}

// ---------------- launch ----------------
extern "C" void kernel_launch(void* const* d_in, const int* in_sizes, int n_in,
                              void* d_out, int out_size) {
    const float* obs = (const float*)d_in[0];
    const float* act = (const float*)d_in[1];
    const float* Wi  = (const float*)d_in[2];
    const float* Wh  = (const float*)d_in[3];
    const float* b   = (const float*)d_in[4];
    const float* mW1 = (const float*)d_in[5],  *mb1 = (const float*)d_in[6];
    const float* mW2 = (const float*)d_in[7],  *mb2 = (const float*)d_in[8];
    const float* mW3 = (const float*)d_in[9],  *mb3 = (const float*)d_in[10];
    const float* lW1 = (const float*)d_in[11], *lb1 = (const float*)d_in[12];
    const float* lW2 = (const float*)d_in[13], *lb2 = (const float*)d_in[14];
    const float* lW3 = (const float*)d_in[15], *lb3 = (const float*)d_in[16];
    float* out = (float*)d_out;

    cudaFuncSetAttribute(lstm_stream_kernel,
                         cudaFuncAttributeMaxDynamicSharedMemorySize, STEP_SMEM);
    cudaFuncSetAttribute(heads_kernel,
                         cudaFuncAttributeMaxDynamicSharedMemorySize, HEADS_SMEM);

    zero_state_kernel<<<512, 256>>>();
    prep_weights_kernel<<<384, 256>>>(Wi, Wh, b);
    prep_x_kernel<<<4096, 256>>>(obs, act);
    lstm_stream_kernel<<<TSTEPS * TILES_PER_STEP, 256, STEP_SMEM>>>();
    heads_kernel<<<BATCH / 128, 128, HEADS_SMEM>>>(mW1, mb1, mW2, mb2, mW3, mb3,
                                                   lW1, lb1, lW2, lb2, lW3, lb3, out);
}

// round 16
// speedup vs baseline: 1.0936x; 1.0262x over previous
#include <cuda_runtime.h>
#include <cuda_fp16.h>
#include <cstdint>

#define BATCH  16384
#define TSTEPS 50
#define HIDDEN 256
#define XCOLS  72       // obs64 | act8, unpadded
#define NSTAGE 5        // 5 x K64 covers k[0,320); tail K8 covers k[320,328)
#define NGATE  1024
#define KTOT   328      // x[0,72) | h[72,328)
#define MTILES 128
#define NTILES 8
#define TILES_PER_STEP (MTILES * NTILES)   // 1024

// ---------------- device scratch ----------------
__device__ __align__(16) __half g_Wb_hi[NGATE * KTOT];
__device__ __align__(16) __half g_Wb_lo[NGATE * KTOT];
__device__ float g_bias[NGATE];
__device__ __align__(16) float  g_c[BATCH * HIDDEN];
__device__ __align__(16) __half g_h[2][BATCH * HIDDEN];
__device__ __align__(16) __half g_x72[(size_t)TSTEPS * BATCH * XCOLS];
__device__ unsigned int g_cnt[TSTEPS * MTILES];   // n-tiles done per (t, mtile)

// ---------------- helpers ----------------
__device__ __forceinline__ uint32_t smem_u32(const void* p) {
    uint32_t a;
    asm("{ .reg .u64 t; cvta.to.shared.u64 t, %1; cvt.u32.u64 %0, t; }" : "=r"(a) : "l"(p));
    return a;
}
__device__ __forceinline__ void cpasync16(uint32_t dst, const void* src) {
    asm volatile("cp.async.cg.shared.global [%0], [%1], 16;" :: "r"(dst), "l"(src));
}
#define CP_COMMIT() asm volatile("cp.async.commit_group;" ::: "memory")
#define CP_WAIT1()  asm volatile("cp.async.wait_group 1;" ::: "memory")
#define CP_WAIT0()  asm volatile("cp.async.wait_group 0;" ::: "memory")

__device__ __forceinline__ void ldsm4(uint32_t* r, uint32_t addr) {
    asm volatile("ldmatrix.sync.aligned.m8n8.x4.shared.b16 {%0,%1,%2,%3}, [%4];"
                 : "=r"(r[0]), "=r"(r[1]), "=r"(r[2]), "=r"(r[3]) : "r"(addr));
}
__device__ __forceinline__ void ldsm2(uint32_t* r, uint32_t addr) {
    asm volatile("ldmatrix.sync.aligned.m8n8.x2.shared.b16 {%0,%1}, [%2];"
                 : "=r"(r[0]), "=r"(r[1]) : "r"(addr));
}
__device__ __forceinline__ void mma16816(float* d, const uint32_t* a, uint32_t b0, uint32_t b1) {
    asm volatile("mma.sync.aligned.m16n8k16.row.col.f32.f16.f16.f32 "
                 "{%0,%1,%2,%3}, {%4,%5,%6,%7}, {%8,%9}, {%0,%1,%2,%3};"
                 : "+f"(d[0]), "+f"(d[1]), "+f"(d[2]), "+f"(d[3])
                 : "r"(a[0]), "r"(a[1]), "r"(a[2]), "r"(a[3]), "r"(b0), "r"(b1));
}
__device__ __forceinline__ float sigm(float x)   { return 1.f / (1.f + __expf(-x)); }
__device__ __forceinline__ float tanhf_(float x) { return 1.f - 2.f / (__expf(2.f * x) + 1.f); }

// ---------------- init kernels ----------------
__global__ void zero_state_kernel() {
    size_t i0 = (size_t)blockIdx.x * blockDim.x + threadIdx.x;
    size_t st = (size_t)gridDim.x * blockDim.x;
    const __half z = __float2half(0.f);
    for (size_t i = i0; i < (size_t)BATCH * HIDDEN; i += st) {
        g_c[i] = 0.f; g_h[0][i] = z;
    }
    for (size_t i = i0; i < TSTEPS * MTILES; i += st) g_cnt[i] = 0u;
}

// Column permutation for warp tile 32x64 over N-tile 128:
// n = nb8*128 + hf*64 + gate*16 + u  ->  orig col gate*256 + nb8*32 + hf*16 + u
// K layout: k<72 -> x (obs|act), k in [72,328) -> h
__global__ void prep_weights_kernel(const float* __restrict__ Wi, const float* __restrict__ Wh,
                                    const float* __restrict__ bias) {
    int i0 = blockIdx.x * blockDim.x + threadIdx.x;
    int st = gridDim.x * blockDim.x;
    for (int idx = i0; idx < NGATE * KTOT; idx += st) {
        int n = idx / KTOT, k = idx - n * KTOT;
        int nb8 = n >> 7, rem = n & 127, hf = rem >> 6, ncol = rem & 63;
        int gate = ncol >> 4, u = ncol & 15;
        int src = gate * 256 + nb8 * 32 + hf * 16 + u;
        float w = (k < 72) ? Wi[k * NGATE + src] : Wh[(k - 72) * NGATE + src];
        __half hi = __float2half_rn(w);
        g_Wb_hi[n * KTOT + k] = hi;
        g_Wb_lo[n * KTOT + k] = __float2half_rn(w - __half2float(hi));
    }
    if (i0 < NGATE) {
        int nb8 = i0 >> 7, rem = i0 & 127, hf = rem >> 6, ncol = rem & 63;
        int gate = ncol >> 4, u = ncol & 15;
        g_bias[i0] = bias[gate * 256 + nb8 * 32 + hf * 16 + u];
    }
}

// g_x72: [t][b][72], obs 0..63 | act 64..71
__global__ void prep_x_kernel(const float* __restrict__ obs, const float* __restrict__ act) {
    size_t i0 = (size_t)blockIdx.x * blockDim.x + threadIdx.x;
    size_t st = (size_t)gridDim.x * blockDim.x;
    const size_t N = (size_t)TSTEPS * BATCH * XCOLS;
    for (size_t i = i0; i < N; i += st) {
        int col = (int)(i % XCOLS);
        size_t m = i / XCOLS;
        int b = (int)(m & (BATCH - 1));
        int t = (int)(m >> 14);
        float v = (col < 64) ? obs[((size_t)b * TSTEPS + t) * 64 + col]
                             : act[((size_t)b * TSTEPS + t) * 8 + (col - 64)];
        g_x72[i] = __float2half_rn(v);
    }
}

// ---------------- streamed LSTM tile kernel ----------------
static constexpr int STG_BYTES = 49152;
static constexpr int S_A    = 0;
static constexpr int S_B_HI = 16384;
static constexpr int S_B_LO = 32768;
static constexpr int S_TAIL = 2 * STG_BYTES;          // 98304
static constexpr int T_A    = 0, T_B_HI = 2048, T_B_LO = 4096;
static constexpr int S_BIAS = S_TAIL + 6144;          // 104448
static constexpr int STEP_SMEM = S_BIAS + 512;        // 104960

// stage s covers k [s*64, s*64+64): k<72 -> x72, else h (k-72)
// with_lo = 0 skips the B_lo tile (stage 0: obs columns, lo-term dropped)
__device__ __forceinline__ void load_stage(
    uint32_t sb, int m0, int nb, int s, int tid, int with_lo,
    const __half* __restrict__ xh, const __half* __restrict__ hin)
{
    const uint32_t base = sb + (uint32_t)(s & 1) * STG_BYTES;
    #pragma unroll
    for (int it = 0; it < 4; it++) {
        int q = tid + it * 256;                 // 1024 quads: 128 rows x 8
        int r = q >> 3, c = q & 7;
        int k = s * 64 + c * 8;
        uint32_t d = (uint32_t)(r * 128) + (uint32_t)((c * 16) ^ ((r & 7) * 16));
        const __half* sa = (k < 72)
            ? xh  + (size_t)(m0 + r) * XCOLS + k
            : hin + (size_t)(m0 + r) * HIDDEN + (k - 72);
        cpasync16(base + S_A + d, sa);
        size_t ob = (size_t)(nb + r) * KTOT + k;
        cpasync16(base + S_B_HI + d, g_Wb_hi + ob);
        if (with_lo) cpasync16(base + S_B_LO + d, g_Wb_lo + ob);
    }
}

// tail: k [320, 328), 128 rows x 8 cols, 16B rows, no swizzle (h-dependent)
__device__ __forceinline__ void load_tail(
    uint32_t sb, int m0, int nb, int tid, const __half* __restrict__ hin)
{
    if (tid < 128) {
        int r = tid;
        cpasync16(sb + S_TAIL + T_A + (uint32_t)(r * 16),
                  hin + (size_t)(m0 + r) * HIDDEN + (320 - 72));
        size_t ob = (size_t)(nb + r) * KTOT + 320;
        cpasync16(sb + S_TAIL + T_B_HI + (uint32_t)(r * 16), g_Wb_hi + ob);
        cpasync16(sb + S_TAIL + T_B_LO + (uint32_t)(r * 16), g_Wb_lo + ob);
    }
}

__global__ __launch_bounds__(256, 2)
void lstm_stream_kernel() {
    extern __shared__ char smem[];
    const int tid = threadIdx.x, w = tid >> 5, lane = tid & 31;
    const int bid = blockIdx.x;
    const int t = bid >> 10;                   // bid / 1024
    const int tile = bid & (TILES_PER_STEP - 1);
    const int mt = tile >> 3, nt = tile & 7;
    const int m0 = mt * 128, nb = nt * 128;
    const int ip = t & 1;
    const __half* __restrict__ hin = g_h[ip];
    __half* __restrict__ hout = g_h[ip ^ 1];

    uint32_t sb = smem_u32(smem);
    float* bias_s = (float*)(smem + S_BIAS);
    if (tid < 128) bias_s[tid] = g_bias[nb + tid];

    const __half* xh = g_x72 + (size_t)t * BATCH * XCOLS;

    // ---- stage 0 (pure-x, hi-only): h-independent, issue before the spin ----
    load_stage(sb, m0, nb, 0, tid, /*with_lo=*/0, xh, hin);
    CP_COMMIT();

    // ---- dependency wait ----
    if (t > 0) {
        if (tid == 0) {
            while (atomicAdd(&g_cnt[(t - 1) * MTILES + mt], 0u) < 8u)
                __nanosleep(64);
            __threadfence();
        }
        __syncthreads();
    }

    load_tail(sb, m0, nb, tid, hin);

    // L2-prefetch this tile's c lines
    if (tid < 128) {
        const float* cp = g_c + (size_t)(m0 + tid) * HIDDEN + nt * 32;
        asm volatile("prefetch.global.L2 [%0];" :: "l"(cp));
    }

    float acc[64];
    #pragma unroll
    for (int i = 0; i < 64; i++) acc[i] = 0.f;

    // warp tile: 32 (M) x 64 (N); 8 warps = 4M x 2N
    const int mwarp = (w >> 1) * 32, nwarp = (w & 1) * 64;
    const int laneA_row = (lane & 7) + ((lane >> 3) & 1) * 8;
    const uint32_t laneA_col = (uint32_t)((lane >> 4) * 16);
    const int laneB_row = (lane & 7) + ((lane >> 4) << 3);
    const uint32_t laneB_col = (uint32_t)(((lane >> 3) & 1) * 16);

    #pragma unroll 1
    for (int s = 0; s < NSTAGE; s++) {
        if (s + 1 < NSTAGE) {
            load_stage(sb, m0, nb, s + 1, tid, /*with_lo=*/1, xh, hin);
            CP_COMMIT();
            CP_WAIT1();
        } else {
            CP_WAIT0();
        }
        __syncthreads();

        const uint32_t base = sb + (uint32_t)(s & 1) * STG_BYTES;
        #pragma unroll
        for (int kk = 0; kk < 4; kk++) {
            uint32_t af[2][4];
            #pragma unroll
            for (int mm = 0; mm < 2; mm++) {
                int rA = mwarp + mm * 16 + laneA_row;
                uint32_t ca = ((uint32_t)(kk * 32) + laneA_col) ^ (uint32_t)((rA & 7) * 16);
                ldsm4(af[mm], base + S_A + (uint32_t)(rA * 128) + ca);
            }
            // process bn in pairs; within a pair, issue a wave of 8 independent
            // hi-MMAs then a wave of 8 lo-MMAs -> accumulator RAW distance 8
            #pragma unroll
            for (int bp = 0; bp < 2; bp++) {
                const int bn0 = bp * 2, bn1 = bp * 2 + 1;
                uint32_t bh0[4], bh1[4], bl0[4], bl1[4];
                {
                    int rB0 = nwarp + bn0 * 16 + laneB_row;
                    int rB1 = nwarp + bn1 * 16 + laneB_row;
                    uint32_t cb0 = ((uint32_t)(kk * 32) + laneB_col) ^ (uint32_t)((rB0 & 7) * 16);
                    uint32_t cb1 = ((uint32_t)(kk * 32) + laneB_col) ^ (uint32_t)((rB1 & 7) * 16);
                    ldsm4(bh0, base + S_B_HI + (uint32_t)(rB0 * 128) + cb0);
                    ldsm4(bh1, base + S_B_HI + (uint32_t)(rB1 * 128) + cb1);
                    if (s != 0) {
                        ldsm4(bl0, base + S_B_LO + (uint32_t)(rB0 * 128) + cb0);
                        ldsm4(bl1, base + S_B_LO + (uint32_t)(rB1 * 128) + cb1);
                    }
                }
                // hi wave: 8 independent MMAs
                #pragma unroll
                for (int mm = 0; mm < 2; mm++) {
                    float* p0 = acc + (mm * 8 + bn0 * 2) * 4;
                    float* p1 = acc + (mm * 8 + bn1 * 2) * 4;
                    mma16816(p0,     af[mm], bh0[0], bh0[1]);
                    mma16816(p0 + 4, af[mm], bh0[2], bh0[3]);
                    mma16816(p1,     af[mm], bh1[0], bh1[1]);
                    mma16816(p1 + 4, af[mm], bh1[2], bh1[3]);
                }
                // lo wave: 8 MMAs, each RAW-depends on a hi-MMA 8 issues earlier
                if (s != 0) {
                    #pragma unroll
                    for (int mm = 0; mm < 2; mm++) {
                        float* p0 = acc + (mm * 8 + bn0 * 2) * 4;
                        float* p1 = acc + (mm * 8 + bn1 * 2) * 4;
                        mma16816(p0,     af[mm], bl0[0], bl0[1]);
                        mma16816(p0 + 4, af[mm], bl0[2], bl0[3]);
                        mma16816(p1,     af[mm], bl1[0], bl1[1]);
                        mma16816(p1 + 4, af[mm], bl1[2], bl1[3]);
                    }
                }
            }
        }
        __syncthreads();
    }

    // ---- tail K8 pass (k 320..327) ----
    {
        const int lrow = lane & 15;
        #pragma unroll
        for (int mm = 0; mm < 2; mm++) {
            int rA = mwarp + mm * 16 + lrow;
            uint32_t a2[2];
            ldsm2(a2, sb + S_TAIL + T_A + (uint32_t)(rA * 16));
            uint32_t aT[4] = {a2[0], a2[1], 0u, 0u};
            #pragma unroll
            for (int bn = 0; bn < 4; bn++) {
                int rB = nwarp + bn * 16 + lrow;
                uint32_t b2h[2], b2l[2];
                ldsm2(b2h, sb + S_TAIL + T_B_HI + (uint32_t)(rB * 16));
                ldsm2(b2l, sb + S_TAIL + T_B_LO + (uint32_t)(rB * 16));
                float* a0 = acc + (mm * 8 + bn * 2) * 4;
                float* a1 = a0 + 4;
                mma16816(a0, aT, b2h[0], 0u);
                mma16816(a0, aT, b2l[0], 0u);
                mma16816(a1, aT, b2h[1], 0u);
                mma16816(a1, aT, b2l[1], 0u);
            }
        }
    }

    // ---- fused LSTM epilogue ----
    const int c = 2 * (lane & 3);
    #pragma unroll
    for (int mm = 0; mm < 2; mm++) {
        #pragma unroll
        for (int rs = 0; rs < 2; rs++) {
            const int row = m0 + mwarp + mm * 16 + (lane >> 2) + rs * 8;
            #pragma unroll
            for (int h8 = 0; h8 < 2; h8++) {
                const int u = h8 * 8 + c;
                const int bcol = nwarp + u;
                float i0 = acc[(mm * 8 + 0 + h8) * 4 + rs * 2 + 0] + bias_s[bcol];
                float i1 = acc[(mm * 8 + 0 + h8) * 4 + rs * 2 + 1] + bias_s[bcol + 1];
                float f0 = acc[(mm * 8 + 2 + h8) * 4 + rs * 2 + 0] + bias_s[bcol + 16];
                float f1 = acc[(mm * 8 + 2 + h8) * 4 + rs * 2 + 1] + bias_s[bcol + 17];
                float g0 = acc[(mm * 8 + 4 + h8) * 4 + rs * 2 + 0] + bias_s[bcol + 32];
                float g1 = acc[(mm * 8 + 4 + h8) * 4 + rs * 2 + 1] + bias_s[bcol + 33];
                float o0 = acc[(mm * 8 + 6 + h8) * 4 + rs * 2 + 0] + bias_s[bcol + 48];
                float o1 = acc[(mm * 8 + 6 + h8) * 4 + rs * 2 + 1] + bias_s[bcol + 49];
                size_t cix = (size_t)row * HIDDEN + nt * 32 + (w & 1) * 16 + u;
                float2 cv = *reinterpret_cast<float2*>(g_c + cix);
                float nc0 = sigm(f0) * cv.x + sigm(i0) * tanhf_(g0);
                float nc1 = sigm(f1) * cv.y + sigm(i1) * tanhf_(g1);
                *reinterpret_cast<float2*>(g_c + cix) = make_float2(nc0, nc1);
                float h0 = sigm(o0) * tanhf_(nc0);
                float h1 = sigm(o1) * tanhf_(nc1);
                *reinterpret_cast<__half2*>(hout + cix) = __floats2half2_rn(h0, h1);
            }
        }
    }

    // ---- signal ----
    __syncthreads();
    if (tid == 0) {
        __threadfence();
        atomicAdd(&g_cnt[t * MTILES + mt], 1u);
    }
}

// ---------------- MLP heads ----------------
static constexpr int H_W1M = 0, H_W2M = 16384, H_W3M = 20480;
static constexpr int H_W1L = 21504, H_W2L = 29696, H_W3L = 30720;
static constexpr int H_B1M = 31232, H_B2M = 31296, H_B3M = 31360;
static constexpr int H_B1L = 31376, H_B2L = 31408, H_B3L = 31440;
static constexpr int HEADS_SMEM = 31456 * 4;

__global__ __launch_bounds__(128, 1)
void heads_kernel(const float* __restrict__ mW1, const float* __restrict__ mb1,
                  const float* __restrict__ mW2, const float* __restrict__ mb2,
                  const float* __restrict__ mW3, const float* __restrict__ mb3,
                  const float* __restrict__ lW1, const float* __restrict__ lb1,
                  const float* __restrict__ lW2, const float* __restrict__ lb2,
                  const float* __restrict__ lW3, const float* __restrict__ lb3,
                  float* __restrict__ out) {
    extern __shared__ float sw[];
    const int tid = threadIdx.x;
    for (int i = tid; i < 16384; i += 128) sw[H_W1M + i] = mW1[i];
    for (int i = tid; i < 4096;  i += 128) sw[H_W2M + i] = mW2[i];
    for (int i = tid; i < 1024;  i += 128) sw[H_W3M + i] = mW3[i];
    for (int i = tid; i < 8192;  i += 128) sw[H_W1L + i] = lW1[i];
    for (int i = tid; i < 1024;  i += 128) sw[H_W2L + i] = lW2[i];
    for (int i = tid; i < 512;   i += 128) sw[H_W3L + i] = lW3[i];
    if (tid < 64) { sw[H_B1M + tid] = mb1[tid]; sw[H_B2M + tid] = mb2[tid]; }
    if (tid < 32) { sw[H_B1L + tid] = lb1[tid]; sw[H_B2L + tid] = lb2[tid]; }
    if (tid < 16) { sw[H_B3M + tid] = mb3[tid]; sw[H_B3L + tid] = lb3[tid]; }
    __syncthreads();

    const int row = blockIdx.x * 128 + tid;
    const __half* hh = g_h[0];   // T=50 even -> final h parity 0
    const size_t hbase = (size_t)row * HIDDEN;

    float x1[64], y1[32];
    #pragma unroll
    for (int j = 0; j < 64; j++) x1[j] = sw[H_B1M + j];
    #pragma unroll
    for (int j = 0; j < 32; j++) y1[j] = sw[H_B1L + j];

    for (int kc = 0; kc < 16; kc++) {
        float hk[16];
        #pragma unroll
        for (int n = 0; n < 16; n++) hk[n] = __half2float(hh[hbase + kc * 16 + n]);
        #pragma unroll
        for (int n = 0; n < 16; n++) {
            const int k = kc * 16 + n;
            #pragma unroll
            for (int j4 = 0; j4 < 16; j4++) {
                float4 wv = *reinterpret_cast<const float4*>(sw + H_W1M + k * 64 + j4 * 4);
                x1[j4*4+0] += hk[n] * wv.x; x1[j4*4+1] += hk[n] * wv.y;
                x1[j4*4+2] += hk[n] * wv.z; x1[j4*4+3] += hk[n] * wv.w;
            }
            #pragma unroll
            for (int j4 = 0; j4 < 8; j4++) {
                float4 wv = *reinterpret_cast<const float4*>(sw + H_W1L + k * 32 + j4 * 4);
                y1[j4*4+0] += hk[n] * wv.x; y1[j4*4+1] += hk[n] * wv.y;
                y1[j4*4+2] += hk[n] * wv.z; y1[j4*4+3] += hk[n] * wv.w;
            }
        }
    }

    float x2[64];
    #pragma unroll
    for (int j = 0; j < 64; j++) { x1[j] = fmaxf(x1[j], 0.f); x2[j] = sw[H_B2M + j]; }
    #pragma unroll
    for (int k = 0; k < 64; k++) {
        #pragma unroll
        for (int j4 = 0; j4 < 16; j4++) {
            float4 wv = *reinterpret_cast<const float4*>(sw + H_W2M + k * 64 + j4 * 4);
            x2[j4*4+0] += x1[k] * wv.x; x2[j4*4+1] += x1[k] * wv.y;
            x2[j4*4+2] += x1[k] * wv.z; x2[j4*4+3] += x1[k] * wv.w;
        }
    }
    float mu[16];
    #pragma unroll
    for (int j = 0; j < 16; j++) mu[j] = sw[H_B3M + j];
    #pragma unroll
    for (int k = 0; k < 64; k++) {
        float xv = fmaxf(x2[k], 0.f);
        #pragma unroll
        for (int j4 = 0; j4 < 4; j4++) {
            float4 wv = *reinterpret_cast<const float4*>(sw + H_W3M + k * 16 + j4 * 4);
            mu[j4*4+0] += xv * wv.x; mu[j4*4+1] += xv * wv.y;
            mu[j4*4+2] += xv * wv.z; mu[j4*4+3] += xv * wv.w;
        }
    }
    #pragma unroll
    for (int j4 = 0; j4 < 4; j4++)
        *reinterpret_cast<float4*>(out + (size_t)row * 16 + j4 * 4) =
            make_float4(mu[j4*4], mu[j4*4+1], mu[j4*4+2], mu[j4*4+3]);

    float y2[32];
    #pragma unroll
    for (int j = 0; j < 32; j++) { y1[j] = fmaxf(y1[j], 0.f); y2[j] = sw[H_B2L + j]; }
    #pragma unroll
    for (int k = 0; k < 32; k++) {
        #pragma unroll
        for (int j4 = 0; j4 < 8; j4++) {
            float4 wv = *reinterpret_cast<const float4*>(sw + H_W2L + k * 32 + j4 * 4);
            y2[j4*4+0] += y1[k] * wv.x; y2[j4*4+1] += y1[k] * wv.y;
            y2[j4*4+2] += y1[k] * wv.z; y2[j4*4+3] += y1[k] * wv.w;
        }
    }
    float ls[16];
    #pragma unroll
    for (int j = 0; j < 16; j++) ls[j] = sw[H_B3L + j];
    #pragma unroll
    for (int k = 0; k < 32; k++) {
        float xv = fmaxf(y2[k], 0.f);
        #pragma unroll
        for (int j4 = 0; j4 < 4; j4++) {
            float4 wv = *reinterpret_cast<const float4*>(sw + H_W3L + k * 16 + j4 * 4);
            ls[j4*4+0] += xv * wv.x; ls[j4*4+1] += xv * wv.y;
            ls[j4*4+2] += xv * wv.z; ls[j4*4+3] += xv * wv.w;
        }
    }
    float* sig = out + (size_t)BATCH * 16 + (size_t)row * 16;
    #pragma unroll
    for (int j = 0; j < 16; j++)
        sig[j] = __expf(fminf(fmaxf(ls[j], -10.f), 2.f));
}

// ---------------- launch ----------------
extern "C" void kernel_launch(void* const* d_in, const int* in_sizes, int n_in,
                              void* d_out, int out_size) {
    const float* obs = (const float*)d_in[0];
    const float* act = (const float*)d_in[1];
    const float* Wi  = (const float*)d_in[2];
    const float* Wh  = (const float*)d_in[3];
    const float* b   = (const float*)d_in[4];
    const float* mW1 = (const float*)d_in[5],  *mb1 = (const float*)d_in[6];
    const float* mW2 = (const float*)d_in[7],  *mb2 = (const float*)d_in[8];
    const float* mW3 = (const float*)d_in[9],  *mb3 = (const float*)d_in[10];
    const float* lW1 = (const float*)d_in[11], *lb1 = (const float*)d_in[12];
    const float* lW2 = (const float*)d_in[13], *lb2 = (const float*)d_in[14];
    const float* lW3 = (const float*)d_in[15], *lb3 = (const float*)d_in[16];
    float* out = (float*)d_out;

    cudaFuncSetAttribute(lstm_stream_kernel,
                         cudaFuncAttributeMaxDynamicSharedMemorySize, STEP_SMEM);
    cudaFuncSetAttribute(heads_kernel,
                         cudaFuncAttributeMaxDynamicSharedMemorySize, HEADS_SMEM);

    zero_state_kernel<<<512, 256>>>();
    prep_weights_kernel<<<384, 256>>>(Wi, Wh, b);
    prep_x_kernel<<<4096, 256>>>(obs, act);
    lstm_stream_kernel<<<TSTEPS * TILES_PER_STEP, 256, STEP_SMEM>>>();
    heads_kernel<<<BATCH / 128, 128, HEADS_SMEM>>>(mW1, mb1, mW2, mb2, mW3, mb3,
                                                   lW1, lb1, lW2, lb2, lW3, lb3, out);
}

// round 17
// speedup vs baseline: 1.0995x; 1.0055x over previous
#include <cuda_runtime.h>
#include <cuda_fp16.h>
#include <cstdint>

#define BATCH  16384
#define TSTEPS 50
#define HIDDEN 256
#define XCOLS  72       // obs64 | act8, unpadded
#define NSTAGE 5        // 5 x K64 covers k[0,320); tail K8 covers k[320,328)
#define NGATE  1024
#define KTOT   328      // x[0,72) | h[72,328)
#define MTILES 128
#define NTILES 8
#define TILES_PER_STEP (MTILES * NTILES)   // 1024

// ---------------- device scratch ----------------
__device__ __align__(16) __half g_Wb_hi[NGATE * KTOT];
__device__ __align__(16) __half g_Wb_lo[NGATE * KTOT];
__device__ float g_bias[NGATE];
__device__ __align__(16) float  g_c[BATCH * HIDDEN];
__device__ __align__(16) __half g_h[2][BATCH * HIDDEN];
__device__ __align__(16) __half g_x72[(size_t)TSTEPS * BATCH * XCOLS];
__device__ unsigned int g_cnt[TSTEPS * MTILES];   // n-tiles done per (t, mtile)

// ---------------- helpers ----------------
__device__ __forceinline__ uint32_t smem_u32(const void* p) {
    uint32_t a;
    asm("{ .reg .u64 t; cvta.to.shared.u64 t, %1; cvt.u32.u64 %0, t; }" : "=r"(a) : "l"(p));
    return a;
}
__device__ __forceinline__ void cpasync16(uint32_t dst, const void* src) {
    asm volatile("cp.async.cg.shared.global [%0], [%1], 16;" :: "r"(dst), "l"(src));
}
#define CP_COMMIT() asm volatile("cp.async.commit_group;" ::: "memory")
#define CP_WAIT1()  asm volatile("cp.async.wait_group 1;" ::: "memory")
#define CP_WAIT0()  asm volatile("cp.async.wait_group 0;" ::: "memory")

__device__ __forceinline__ void ldsm4(uint32_t* r, uint32_t addr) {
    asm volatile("ldmatrix.sync.aligned.m8n8.x4.shared.b16 {%0,%1,%2,%3}, [%4];"
                 : "=r"(r[0]), "=r"(r[1]), "=r"(r[2]), "=r"(r[3]) : "r"(addr));
}
__device__ __forceinline__ void ldsm2(uint32_t* r, uint32_t addr) {
    asm volatile("ldmatrix.sync.aligned.m8n8.x2.shared.b16 {%0,%1}, [%2];"
                 : "=r"(r[0]), "=r"(r[1]) : "r"(addr));
}
__device__ __forceinline__ void mma16816(float* d, const uint32_t* a, uint32_t b0, uint32_t b1) {
    asm volatile("mma.sync.aligned.m16n8k16.row.col.f32.f16.f16.f32 "
                 "{%0,%1,%2,%3}, {%4,%5,%6,%7}, {%8,%9}, {%0,%1,%2,%3};"
                 : "+f"(d[0]), "+f"(d[1]), "+f"(d[2]), "+f"(d[3])
                 : "r"(a[0]), "r"(a[1]), "r"(a[2]), "r"(a[3]), "r"(b0), "r"(b1));
}
__device__ __forceinline__ float sigm(float x)   { return 1.f / (1.f + __expf(-x)); }
__device__ __forceinline__ float tanhf_(float x) { return 1.f - 2.f / (__expf(2.f * x) + 1.f); }

// ---------------- init kernels ----------------
__global__ void zero_state_kernel() {
    size_t i0 = (size_t)blockIdx.x * blockDim.x + threadIdx.x;
    size_t st = (size_t)gridDim.x * blockDim.x;
    const __half z = __float2half(0.f);
    for (size_t i = i0; i < (size_t)BATCH * HIDDEN; i += st) {
        g_c[i] = 0.f; g_h[0][i] = z;
    }
    for (size_t i = i0; i < TSTEPS * MTILES; i += st) g_cnt[i] = 0u;
}

// Column permutation for warp tile 32x64 over N-tile 128:
// n = nb8*128 + hf*64 + gate*16 + u  ->  orig col gate*256 + nb8*32 + hf*16 + u
// K layout: k<72 -> x (obs|act), k in [72,328) -> h
__global__ void prep_weights_kernel(const float* __restrict__ Wi, const float* __restrict__ Wh,
                                    const float* __restrict__ bias) {
    int i0 = blockIdx.x * blockDim.x + threadIdx.x;
    int st = gridDim.x * blockDim.x;
    for (int idx = i0; idx < NGATE * KTOT; idx += st) {
        int n = idx / KTOT, k = idx - n * KTOT;
        int nb8 = n >> 7, rem = n & 127, hf = rem >> 6, ncol = rem & 63;
        int gate = ncol >> 4, u = ncol & 15;
        int src = gate * 256 + nb8 * 32 + hf * 16 + u;
        float w = (k < 72) ? Wi[k * NGATE + src] : Wh[(k - 72) * NGATE + src];
        __half hi = __float2half_rn(w);
        g_Wb_hi[n * KTOT + k] = hi;
        g_Wb_lo[n * KTOT + k] = __float2half_rn(w - __half2float(hi));
    }
    if (i0 < NGATE) {
        int nb8 = i0 >> 7, rem = i0 & 127, hf = rem >> 6, ncol = rem & 63;
        int gate = ncol >> 4, u = ncol & 15;
        g_bias[i0] = bias[gate * 256 + nb8 * 32 + hf * 16 + u];
    }
}

// g_x72: [t][b][72], obs 0..63 | act 64..71
__global__ void prep_x_kernel(const float* __restrict__ obs, const float* __restrict__ act) {
    size_t i0 = (size_t)blockIdx.x * blockDim.x + threadIdx.x;
    size_t st = (size_t)gridDim.x * blockDim.x;
    const size_t N = (size_t)TSTEPS * BATCH * XCOLS;
    for (size_t i = i0; i < N; i += st) {
        int col = (int)(i % XCOLS);
        size_t m = i / XCOLS;
        int b = (int)(m & (BATCH - 1));
        int t = (int)(m >> 14);
        float v = (col < 64) ? obs[((size_t)b * TSTEPS + t) * 64 + col]
                             : act[((size_t)b * TSTEPS + t) * 8 + (col - 64)];
        g_x72[i] = __float2half_rn(v);
    }
}

// ---------------- streamed LSTM tile kernel ----------------
static constexpr int STG_BYTES = 49152;
static constexpr int S_A    = 0;
static constexpr int S_B_HI = 16384;
static constexpr int S_B_LO = 32768;
static constexpr int S_TAIL = 2 * STG_BYTES;          // 98304
static constexpr int T_A    = 0, T_B_HI = 2048, T_B_LO = 4096;
static constexpr int S_BIAS = S_TAIL + 6144;          // 104448
static constexpr int STEP_SMEM = S_BIAS + 512;        // 104960

// stage s covers k [s*64, s*64+64): k<72 -> x72, else h (k-72)
// with_lo = 0 skips the B_lo tile (stage 0: obs columns, lo-term dropped)
__device__ __forceinline__ void load_stage(
    uint32_t sb, int m0, int nb, int s, int tid, int with_lo,
    const __half* __restrict__ xh, const __half* __restrict__ hin)
{
    const uint32_t base = sb + (uint32_t)(s & 1) * STG_BYTES;
    #pragma unroll
    for (int it = 0; it < 4; it++) {
        int q = tid + it * 256;                 // 1024 quads: 128 rows x 8
        int r = q >> 3, c = q & 7;
        int k = s * 64 + c * 8;
        uint32_t d = (uint32_t)(r * 128) + (uint32_t)((c * 16) ^ ((r & 7) * 16));
        const __half* sa = (k < 72)
            ? xh  + (size_t)(m0 + r) * XCOLS + k
            : hin + (size_t)(m0 + r) * HIDDEN + (k - 72);
        cpasync16(base + S_A + d, sa);
        size_t ob = (size_t)(nb + r) * KTOT + k;
        cpasync16(base + S_B_HI + d, g_Wb_hi + ob);
        if (with_lo) cpasync16(base + S_B_LO + d, g_Wb_lo + ob);
    }
}

// tail: k [320, 328), 128 rows x 8 cols, 16B rows, no swizzle (h-dependent)
__device__ __forceinline__ void load_tail(
    uint32_t sb, int m0, int nb, int tid, const __half* __restrict__ hin)
{
    if (tid < 128) {
        int r = tid;
        cpasync16(sb + S_TAIL + T_A + (uint32_t)(r * 16),
                  hin + (size_t)(m0 + r) * HIDDEN + (320 - 72));
        size_t ob = (size_t)(nb + r) * KTOT + 320;
        cpasync16(sb + S_TAIL + T_B_HI + (uint32_t)(r * 16), g_Wb_hi + ob);
        cpasync16(sb + S_TAIL + T_B_LO + (uint32_t)(r * 16), g_Wb_lo + ob);
    }
}

__global__ __launch_bounds__(256, 2)
void lstm_stream_kernel() {
    extern __shared__ char smem[];
    const int tid = threadIdx.x, w = tid >> 5, lane = tid & 31;
    const int bid = blockIdx.x;
    const int t = bid >> 10;                   // bid / 1024
    const int tile = bid & (TILES_PER_STEP - 1);
    const int mt = tile >> 3, nt = tile & 7;
    const int m0 = mt * 128, nb = nt * 128;
    const int ip = t & 1;
    const __half* __restrict__ hin = g_h[ip];
    __half* __restrict__ hout = g_h[ip ^ 1];

    uint32_t sb = smem_u32(smem);
    float* bias_s = (float*)(smem + S_BIAS);
    if (tid < 128) bias_s[tid] = g_bias[nb + tid];

    const __half* xh = g_x72 + (size_t)t * BATCH * XCOLS;

    // ---- stage 0 (pure-x, hi-only): h-independent, issue before the spin ----
    load_stage(sb, m0, nb, 0, tid, /*with_lo=*/0, xh, hin);
    CP_COMMIT();

    // ---- dependency wait ----
    if (t > 0) {
        if (tid == 0) {
            while (atomicAdd(&g_cnt[(t - 1) * MTILES + mt], 0u) < 8u)
                __nanosleep(64);
            __threadfence();
        }
        __syncthreads();
    }

    load_tail(sb, m0, nb, tid, hin);

    // L2-prefetch this tile's c lines
    if (tid < 128) {
        const float* cp = g_c + (size_t)(m0 + tid) * HIDDEN + nt * 32;
        asm volatile("prefetch.global.L2 [%0];" :: "l"(cp));
    }

    float acc[64];
    #pragma unroll
    for (int i = 0; i < 64; i++) acc[i] = 0.f;

    // warp tile: 32 (M) x 64 (N); 8 warps = 4M x 2N
    const int mwarp = (w >> 1) * 32, nwarp = (w & 1) * 64;
    const int laneA_row = (lane & 7) + ((lane >> 3) & 1) * 8;
    const uint32_t laneA_col = (uint32_t)((lane >> 4) * 16);
    const int laneB_row = (lane & 7) + ((lane >> 4) << 3);
    const uint32_t laneB_col = (uint32_t)(((lane >> 3) & 1) * 16);

    #pragma unroll 1
    for (int s = 0; s < NSTAGE; s++) {
        if (s + 1 < NSTAGE) {
            load_stage(sb, m0, nb, s + 1, tid, /*with_lo=*/1, xh, hin);
            CP_COMMIT();
            CP_WAIT1();
        } else {
            CP_WAIT0();
        }
        __syncthreads();

        const uint32_t base = sb + (uint32_t)(s & 1) * STG_BYTES;
        #pragma unroll
        for (int kk = 0; kk < 4; kk++) {
            uint32_t af[2][4];
            #pragma unroll
            for (int mm = 0; mm < 2; mm++) {
                int rA = mwarp + mm * 16 + laneA_row;
                uint32_t ca = ((uint32_t)(kk * 32) + laneA_col) ^ (uint32_t)((rA & 7) * 16);
                ldsm4(af[mm], base + S_A + (uint32_t)(rA * 128) + ca);
            }
            // B fragment byte offsets per bn (shared between hi and lo tiles)
            uint32_t boff[4];
            #pragma unroll
            for (int bn = 0; bn < 4; bn++) {
                int rB = nwarp + bn * 16 + laneB_row;
                boff[bn] = (uint32_t)(rB * 128) +
                           (((uint32_t)(kk * 32) + laneB_col) ^ (uint32_t)((rB & 7) * 16));
            }
            // hi wave: load all 4 bn fragments, then 16 independent MMAs
            uint32_t bb[4][4];
            #pragma unroll
            for (int bn = 0; bn < 4; bn++) ldsm4(bb[bn], base + S_B_HI + boff[bn]);
            #pragma unroll
            for (int mm = 0; mm < 2; mm++) {
                #pragma unroll
                for (int bn = 0; bn < 4; bn++) {
                    float* p = acc + (mm * 8 + bn * 2) * 4;
                    mma16816(p,     af[mm], bb[bn][0], bb[bn][1]);
                    mma16816(p + 4, af[mm], bb[bn][2], bb[bn][3]);
                }
            }
            // lo wave: reuse the same registers; each MMA's accumulator RAW is 16 back
            if (s != 0) {
                #pragma unroll
                for (int bn = 0; bn < 4; bn++) ldsm4(bb[bn], base + S_B_LO + boff[bn]);
                #pragma unroll
                for (int mm = 0; mm < 2; mm++) {
                    #pragma unroll
                    for (int bn = 0; bn < 4; bn++) {
                        float* p = acc + (mm * 8 + bn * 2) * 4;
                        mma16816(p,     af[mm], bb[bn][0], bb[bn][1]);
                        mma16816(p + 4, af[mm], bb[bn][2], bb[bn][3]);
                    }
                }
            }
        }
        __syncthreads();
    }

    // ---- tail K8 pass (k 320..327) ----
    {
        const int lrow = lane & 15;
        #pragma unroll
        for (int mm = 0; mm < 2; mm++) {
            int rA = mwarp + mm * 16 + lrow;
            uint32_t a2[2];
            ldsm2(a2, sb + S_TAIL + T_A + (uint32_t)(rA * 16));
            uint32_t aT[4] = {a2[0], a2[1], 0u, 0u};
            #pragma unroll
            for (int bn = 0; bn < 4; bn++) {
                int rB = nwarp + bn * 16 + lrow;
                uint32_t b2h[2], b2l[2];
                ldsm2(b2h, sb + S_TAIL + T_B_HI + (uint32_t)(rB * 16));
                ldsm2(b2l, sb + S_TAIL + T_B_LO + (uint32_t)(rB * 16));
                float* a0 = acc + (mm * 8 + bn * 2) * 4;
                float* a1 = a0 + 4;
                mma16816(a0, aT, b2h[0], 0u);
                mma16816(a0, aT, b2l[0], 0u);
                mma16816(a1, aT, b2h[1], 0u);
                mma16816(a1, aT, b2l[1], 0u);
            }
        }
    }

    // ---- fused LSTM epilogue ----
    const int c = 2 * (lane & 3);
    #pragma unroll
    for (int mm = 0; mm < 2; mm++) {
        #pragma unroll
        for (int rs = 0; rs < 2; rs++) {
            const int row = m0 + mwarp + mm * 16 + (lane >> 2) + rs * 8;
            #pragma unroll
            for (int h8 = 0; h8 < 2; h8++) {
                const int u = h8 * 8 + c;
                const int bcol = nwarp + u;
                float i0 = acc[(mm * 8 + 0 + h8) * 4 + rs * 2 + 0] + bias_s[bcol];
                float i1 = acc[(mm * 8 + 0 + h8) * 4 + rs * 2 + 1] + bias_s[bcol + 1];
                float f0 = acc[(mm * 8 + 2 + h8) * 4 + rs * 2 + 0] + bias_s[bcol + 16];
                float f1 = acc[(mm * 8 + 2 + h8) * 4 + rs * 2 + 1] + bias_s[bcol + 17];
                float g0 = acc[(mm * 8 + 4 + h8) * 4 + rs * 2 + 0] + bias_s[bcol + 32];
                float g1 = acc[(mm * 8 + 4 + h8) * 4 + rs * 2 + 1] + bias_s[bcol + 33];
                float o0 = acc[(mm * 8 + 6 + h8) * 4 + rs * 2 + 0] + bias_s[bcol + 48];
                float o1 = acc[(mm * 8 + 6 + h8) * 4 + rs * 2 + 1] + bias_s[bcol + 49];
                size_t cix = (size_t)row * HIDDEN + nt * 32 + (w & 1) * 16 + u;
                float2 cv = *reinterpret_cast<float2*>(g_c + cix);
                float nc0 = sigm(f0) * cv.x + sigm(i0) * tanhf_(g0);
                float nc1 = sigm(f1) * cv.y + sigm(i1) * tanhf_(g1);
                *reinterpret_cast<float2*>(g_c + cix) = make_float2(nc0, nc1);
                float h0 = sigm(o0) * tanhf_(nc0);
                float h1 = sigm(o1) * tanhf_(nc1);
                *reinterpret_cast<__half2*>(hout + cix) = __floats2half2_rn(h0, h1);
            }
        }
    }

    // ---- signal ----
    __syncthreads();
    if (tid == 0) {
        __threadfence();
        atomicAdd(&g_cnt[t * MTILES + mt], 1u);
    }
}

// ---------------- MLP heads ----------------
static constexpr int H_W1M = 0, H_W2M = 16384, H_W3M = 20480;
static constexpr int H_W1L = 21504, H_W2L = 29696, H_W3L = 30720;
static constexpr int H_B1M = 31232, H_B2M = 31296, H_B3M = 31360;
static constexpr int H_B1L = 31376, H_B2L = 31408, H_B3L = 31440;
static constexpr int HEADS_SMEM = 31456 * 4;

__global__ __launch_bounds__(128, 1)
void heads_kernel(const float* __restrict__ mW1, const float* __restrict__ mb1,
                  const float* __restrict__ mW2, const float* __restrict__ mb2,
                  const float* __restrict__ mW3, const float* __restrict__ mb3,
                  const float* __restrict__ lW1, const float* __restrict__ lb1,
                  const float* __restrict__ lW2, const float* __restrict__ lb2,
                  const float* __restrict__ lW3, const float* __restrict__ lb3,
                  float* __restrict__ out) {
    extern __shared__ float sw[];
    const int tid = threadIdx.x;
    for (int i = tid; i < 16384; i += 128) sw[H_W1M + i] = mW1[i];
    for (int i = tid; i < 4096;  i += 128) sw[H_W2M + i] = mW2[i];
    for (int i = tid; i < 1024;  i += 128) sw[H_W3M + i] = mW3[i];
    for (int i = tid; i < 8192;  i += 128) sw[H_W1L + i] = lW1[i];
    for (int i = tid; i < 1024;  i += 128) sw[H_W2L + i] = lW2[i];
    for (int i = tid; i < 512;   i += 128) sw[H_W3L + i] = lW3[i];
    if (tid < 64) { sw[H_B1M + tid] = mb1[tid]; sw[H_B2M + tid] = mb2[tid]; }
    if (tid < 32) { sw[H_B1L + tid] = lb1[tid]; sw[H_B2L + tid] = lb2[tid]; }
    if (tid < 16) { sw[H_B3M + tid] = mb3[tid]; sw[H_B3L + tid] = lb3[tid]; }
    __syncthreads();

    const int row = blockIdx.x * 128 + tid;
    const __half* hh = g_h[0];   // T=50 even -> final h parity 0
    const size_t hbase = (size_t)row * HIDDEN;

    float x1[64], y1[32];
    #pragma unroll
    for (int j = 0; j < 64; j++) x1[j] = sw[H_B1M + j];
    #pragma unroll
    for (int j = 0; j < 32; j++) y1[j] = sw[H_B1L + j];

    for (int kc = 0; kc < 16; kc++) {
        float hk[16];
        #pragma unroll
        for (int n = 0; n < 16; n++) hk[n] = __half2float(hh[hbase + kc * 16 + n]);
        #pragma unroll
        for (int n = 0; n < 16; n++) {
            const int k = kc * 16 + n;
            #pragma unroll
            for (int j4 = 0; j4 < 16; j4++) {
                float4 wv = *reinterpret_cast<const float4*>(sw + H_W1M + k * 64 + j4 * 4);
                x1[j4*4+0] += hk[n] * wv.x; x1[j4*4+1] += hk[n] * wv.y;
                x1[j4*4+2] += hk[n] * wv.z; x1[j4*4+3] += hk[n] * wv.w;
            }
            #pragma unroll
            for (int j4 = 0; j4 < 8; j4++) {
                float4 wv = *reinterpret_cast<const float4*>(sw + H_W1L + k * 32 + j4 * 4);
                y1[j4*4+0] += hk[n] * wv.x; y1[j4*4+1] += hk[n] * wv.y;
                y1[j4*4+2] += hk[n] * wv.z; y1[j4*4+3] += hk[n] * wv.w;
            }
        }
    }

    float x2[64];
    #pragma unroll
    for (int j = 0; j < 64; j++) { x1[j] = fmaxf(x1[j], 0.f); x2[j] = sw[H_B2M + j]; }
    #pragma unroll
    for (int k = 0; k < 64; k++) {
        #pragma unroll
        for (int j4 = 0; j4 < 16; j4++) {
            float4 wv = *reinterpret_cast<const float4*>(sw + H_W2M + k * 64 + j4 * 4);
            x2[j4*4+0] += x1[k] * wv.x; x2[j4*4+1] += x1[k] * wv.y;
            x2[j4*4+2] += x1[k] * wv.z; x2[j4*4+3] += x1[k] * wv.w;
        }
    }
    float mu[16];
    #pragma unroll
    for (int j = 0; j < 16; j++) mu[j] = sw[H_B3M + j];
    #pragma unroll
    for (int k = 0; k < 64; k++) {
        float xv = fmaxf(x2[k], 0.f);
        #pragma unroll
        for (int j4 = 0; j4 < 4; j4++) {
            float4 wv = *reinterpret_cast<const float4*>(sw + H_W3M + k * 16 + j4 * 4);
            mu[j4*4+0] += xv * wv.x; mu[j4*4+1] += xv * wv.y;
            mu[j4*4+2] += xv * wv.z; mu[j4*4+3] += xv * wv.w;
        }
    }
    #pragma unroll
    for (int j4 = 0; j4 < 4; j4++)
        *reinterpret_cast<float4*>(out + (size_t)row * 16 + j4 * 4) =
            make_float4(mu[j4*4], mu[j4*4+1], mu[j4*4+2], mu[j4*4+3]);

    float y2[32];
    #pragma unroll
    for (int j = 0; j < 32; j++) { y1[j] = fmaxf(y1[j], 0.f); y2[j] = sw[H_B2L + j]; }
    #pragma unroll
    for (int k = 0; k < 32; k++) {
        #pragma unroll
        for (int j4 = 0; j4 < 8; j4++) {
            float4 wv = *reinterpret_cast<const float4*>(sw + H_W2L + k * 32 + j4 * 4);
            y2[j4*4+0] += y1[k] * wv.x; y2[j4*4+1] += y1[k] * wv.y;
            y2[j4*4+2] += y1[k] * wv.z; y2[j4*4+3] += y1[k] * wv.w;
        }
    }
    float ls[16];
    #pragma unroll
    for (int j = 0; j < 16; j++) ls[j] = sw[H_B3L + j];
    #pragma unroll
    for (int k = 0; k < 32; k++) {
        float xv = fmaxf(y2[k], 0.f);
        #pragma unroll
        for (int j4 = 0; j4 < 4; j4++) {
            float4 wv = *reinterpret_cast<const float4*>(sw + H_W3L + k * 16 + j4 * 4);
            ls[j4*4+0] += xv * wv.x; ls[j4*4+1] += xv * wv.y;
            ls[j4*4+2] += xv * wv.z; ls[j4*4+3] += xv * wv.w;
        }
    }
    float* sig = out + (size_t)BATCH * 16 + (size_t)row * 16;
    #pragma unroll
    for (int j = 0; j < 16; j++)
        sig[j] = __expf(fminf(fmaxf(ls[j], -10.f), 2.f));
}

// ---------------- launch ----------------
extern "C" void kernel_launch(void* const* d_in, const int* in_sizes, int n_in,
                              void* d_out, int out_size) {
    const float* obs = (const float*)d_in[0];
    const float* act = (const float*)d_in[1];
    const float* Wi  = (const float*)d_in[2];
    const float* Wh  = (const float*)d_in[3];
    const float* b   = (const float*)d_in[4];
    const float* mW1 = (const float*)d_in[5],  *mb1 = (const float*)d_in[6];
    const float* mW2 = (const float*)d_in[7],  *mb2 = (const float*)d_in[8];
    const float* mW3 = (const float*)d_in[9],  *mb3 = (const float*)d_in[10];
    const float* lW1 = (const float*)d_in[11], *lb1 = (const float*)d_in[12];
    const float* lW2 = (const float*)d_in[13], *lb2 = (const float*)d_in[14];
    const float* lW3 = (const float*)d_in[15], *lb3 = (const float*)d_in[16];
    float* out = (float*)d_out;

    cudaFuncSetAttribute(lstm_stream_kernel,
                         cudaFuncAttributeMaxDynamicSharedMemorySize, STEP_SMEM);
    cudaFuncSetAttribute(heads_kernel,
                         cudaFuncAttributeMaxDynamicSharedMemorySize, HEADS_SMEM);

    zero_state_kernel<<<512, 256>>>();
    prep_weights_kernel<<<384, 256>>>(Wi, Wh, b);
    prep_x_kernel<<<4096, 256>>>(obs, act);
    lstm_stream_kernel<<<TSTEPS * TILES_PER_STEP, 256, STEP_SMEM>>>();
    heads_kernel<<<BATCH / 128, 128, HEADS_SMEM>>>(mW1, mb1, mW2, mb2, mW3, mb3,
                                                   lW1, lb1, lW2, lb2, lW3, lb3, out);
}